// round 1
// baseline (speedup 1.0000x reference)
#include <cuda_runtime.h>
#include <math.h>

#define EMB   1024
#define HID   4096
#define NH    16
#define DKH   64
#define SQ    2048
#define BATCH 2
#define MTOT  (BATCH*SQ)   // 4096 rows

// ---------------- scratch (device globals: allocation-free) ----------------
__device__ float g_xn[(size_t)MTOT*EMB];
__device__ float g_q [(size_t)MTOT*EMB];
__device__ float g_k [(size_t)MTOT*EMB];
__device__ float g_v [(size_t)MTOT*EMB];
__device__ float g_at[(size_t)MTOT*EMB];
__device__ float g_h [(size_t)MTOT*EMB];
__device__ float g_hn[(size_t)MTOT*EMB];
__device__ float g_ac[(size_t)MTOT*HID];

// ---------------- LayerNorm (faithful: Bessel var, /(std+eps)) -------------
__global__ void ln_kernel(const float* __restrict__ in,
                          const float* __restrict__ alpha,
                          const float* __restrict__ beta,
                          float* __restrict__ out)
{
    __shared__ float row[EMB];
    __shared__ float red[8];
    const int r   = blockIdx.x;
    const int tid = threadIdx.x;
    const float* p = in + (size_t)r * EMB;

    float s = 0.f;
    #pragma unroll
    for (int i = tid; i < EMB; i += 256) { float v = p[i]; row[i] = v; s += v; }
    #pragma unroll
    for (int o = 16; o; o >>= 1) s += __shfl_xor_sync(0xffffffffu, s, o);
    if ((tid & 31) == 0) red[tid >> 5] = s;
    __syncthreads();
    if (tid < 8) {
        float t = red[tid];
        #pragma unroll
        for (int o = 4; o; o >>= 1) t += __shfl_xor_sync(0xffu, t, o);
        if (tid == 0) red[0] = t;
    }
    __syncthreads();
    const float mean = red[0] * (1.f / EMB);

    float s2 = 0.f;
    #pragma unroll
    for (int i = tid; i < EMB; i += 256) { float d = row[i] - mean; s2 += d * d; }
    #pragma unroll
    for (int o = 16; o; o >>= 1) s2 += __shfl_xor_sync(0xffffffffu, s2, o);
    __syncthreads();                       // everyone done reading red[0]
    if ((tid & 31) == 0) red[tid >> 5] = s2;
    __syncthreads();
    if (tid < 8) {
        float t = red[tid];
        #pragma unroll
        for (int o = 4; o; o >>= 1) t += __shfl_xor_sync(0xffu, t, o);
        if (tid == 0) red[0] = t;
    }
    __syncthreads();
    const float var   = red[0] * (1.f / (EMB - 1));
    const float scale = alpha[0] / (sqrtf(var) + 1e-6f);
    const float bias  = beta[0];

    float* op = out + (size_t)r * EMB;
    #pragma unroll
    for (int i = tid; i < EMB; i += 256) op[i] = (row[i] - mean) * scale + bias;
}

// ---------------- SGEMM: C = A[M,K] @ B[K,N] (+bias)(+relu)(+res) ----------
// 128x128 tile, BK=8, 256 threads, 8x8 per thread.
template<int BIAS, int RELU, int RES>
__global__ void __launch_bounds__(256, 2) sgemm_k(
    const float* __restrict__ A, const float* __restrict__ B,
    const float* __restrict__ bias, const float* __restrict__ res,
    float* __restrict__ C, int M, int N, int K)
{
    __shared__ float As[8][128];
    __shared__ float Bs[8][128];
    const int bm = blockIdx.y * 128, bn = blockIdx.x * 128;
    const int tid = threadIdx.x;
    const int tx = tid & 15, ty = tid >> 4;
    const int arow = tid >> 1,  acol = (tid & 1) * 4;
    const int brow = tid >> 5,  bcol = (tid & 31) * 4;
    const float* Ap = A + (size_t)(bm + arow) * K + acol;
    const float* Bp = B + (size_t)brow * N + bn + bcol;

    float acc[8][8];
    #pragma unroll
    for (int i = 0; i < 8; i++)
        #pragma unroll
        for (int j = 0; j < 8; j++) acc[i][j] = 0.f;

    for (int k0 = 0; k0 < K; k0 += 8) {
        float4 av = *(const float4*)(Ap + k0);
        float4 bv = *(const float4*)(Bp + (size_t)k0 * N);
        As[acol + 0][arow] = av.x;
        As[acol + 1][arow] = av.y;
        As[acol + 2][arow] = av.z;
        As[acol + 3][arow] = av.w;
        *(float4*)&Bs[brow][bcol] = bv;
        __syncthreads();
        #pragma unroll
        for (int kk = 0; kk < 8; kk++) {
            float a[8], b[8];
            *(float4*)&a[0] = *(const float4*)&As[kk][ty * 8];
            *(float4*)&a[4] = *(const float4*)&As[kk][ty * 8 + 4];
            *(float4*)&b[0] = *(const float4*)&Bs[kk][tx * 8];
            *(float4*)&b[4] = *(const float4*)&Bs[kk][tx * 8 + 4];
            #pragma unroll
            for (int i = 0; i < 8; i++)
                #pragma unroll
                for (int j = 0; j < 8; j++)
                    acc[i][j] = fmaf(a[i], b[j], acc[i][j]);
        }
        __syncthreads();
    }

    #pragma unroll
    for (int i = 0; i < 8; i++) {
        const int row = bm + ty * 8 + i;
        float* Crow = C + (size_t)row * N + bn + tx * 8;
        const float* Rrow = res + (size_t)row * N + bn + tx * 8;  // unused if !RES
        #pragma unroll
        for (int j = 0; j < 8; j++) {
            float v = acc[i][j];
            if (BIAS) v += bias[bn + tx * 8 + j];
            if (RELU) v = fmaxf(v, 0.f);
            if (RES)  v += Rrow[j];
            Crow[j] = v;
        }
    }
}

// ---------------- flash attention, fp32, 64-query tiles --------------------
__global__ void __launch_bounds__(256, 2) attn_kernel(
    const float* __restrict__ Q, const float* __restrict__ Kg,
    const float* __restrict__ Vg, const int* __restrict__ mask,
    float* __restrict__ O)
{
    __shared__ float Qt[64][64];   // [d][q]  transposed
    __shared__ float KP[64 * 64];  // Kt [d][j]  aliased with Ps [i][j]
    __shared__ float Vs[64][64];   // [j][d]
    const int b  = blockIdx.z, h = blockIdx.y;
    const int q0 = blockIdx.x * 64;
    const int tid = threadIdx.x;
    const int tx = tid & 15, ty = tid >> 4;
    const size_t base = (size_t)b * SQ * EMB + (size_t)h * DKH;

    // load Q tile transposed (conflict-free reads later)
    {
        const int j = tid & 63, d4 = tid >> 6;
        #pragma unroll
        for (int it = 0; it < 4; it++) {
            const int d = (d4 + it * 4) * 4;
            float4 v = *(const float4*)(Q + base + (size_t)(q0 + j) * EMB + d);
            Qt[d + 0][j] = v.x; Qt[d + 1][j] = v.y;
            Qt[d + 2][j] = v.z; Qt[d + 3][j] = v.w;
        }
    }

    float m_r[4], l_r[4], o_acc[4][4];
    #pragma unroll
    for (int a = 0; a < 4; a++) {
        m_r[a] = -1e30f; l_r[a] = 0.f;
        #pragma unroll
        for (int c = 0; c < 4; c++) o_acc[a][c] = 0.f;
    }

    float* Kt = KP;   // [d*64 + j]
    float* Ps = KP;   // [i*64 + j]
    const float scale = 0.125f;   // 1/sqrt(64)

    for (int j0 = 0; j0 < SQ; j0 += 64) {
        // K transposed + V row-major
        {
            const int j = tid & 63, d4 = tid >> 6;
            #pragma unroll
            for (int it = 0; it < 4; it++) {
                const int d = (d4 + it * 4) * 4;
                float4 v = *(const float4*)(Kg + base + (size_t)(j0 + j) * EMB + d);
                Kt[(d + 0) * 64 + j] = v.x; Kt[(d + 1) * 64 + j] = v.y;
                Kt[(d + 2) * 64 + j] = v.z; Kt[(d + 3) * 64 + j] = v.w;
            }
            const int r = tid >> 4, c4 = (tid & 15) * 4;
            #pragma unroll
            for (int it = 0; it < 4; it++) {
                const int j2 = r + it * 16;
                *(float4*)&Vs[j2][c4] =
                    *(const float4*)(Vg + base + (size_t)(j0 + j2) * EMB + c4);
            }
        }
        __syncthreads();

        // S = Q K^T (this 64x64 tile)
        float s[4][4];
        #pragma unroll
        for (int a = 0; a < 4; a++)
            #pragma unroll
            for (int c = 0; c < 4; c++) s[a][c] = 0.f;
        #pragma unroll 8
        for (int d = 0; d < 64; d++) {
            float qv[4], kv[4];
            #pragma unroll
            for (int a = 0; a < 4; a++) qv[a] = Qt[d][ty + 16 * a];
            #pragma unroll
            for (int c = 0; c < 4; c++) kv[c] = Kt[d * 64 + tx + 16 * c];
            #pragma unroll
            for (int a = 0; a < 4; a++)
                #pragma unroll
                for (int c = 0; c < 4; c++)
                    s[a][c] = fmaf(qv[a], kv[c], s[a][c]);
        }
        // scale + mask
        int mk[4];
        #pragma unroll
        for (int c = 0; c < 4; c++) mk[c] = mask[b * SQ + j0 + tx + 16 * c];
        #pragma unroll
        for (int a = 0; a < 4; a++)
            #pragma unroll
            for (int c = 0; c < 4; c++)
                s[a][c] = (mk[c] == 0) ? -1e30f : s[a][c] * scale;

        __syncthreads();   // done with Kt, about to overwrite with Ps

        // online softmax (row state redundant across the 16 tx lanes)
        #pragma unroll
        for (int a = 0; a < 4; a++) {
            float tm = fmaxf(fmaxf(s[a][0], s[a][1]), fmaxf(s[a][2], s[a][3]));
            #pragma unroll
            for (int o = 8; o; o >>= 1) tm = fmaxf(tm, __shfl_xor_sync(0xffffffffu, tm, o));
            const float mn   = fmaxf(m_r[a], tm);
            const float corr = __expf(m_r[a] - mn);
            float ts = 0.f;
            #pragma unroll
            for (int c = 0; c < 4; c++) { float p = __expf(s[a][c] - mn); s[a][c] = p; ts += p; }
            #pragma unroll
            for (int o = 8; o; o >>= 1) ts += __shfl_xor_sync(0xffffffffu, ts, o);
            l_r[a] = l_r[a] * corr + ts;
            m_r[a] = mn;
            #pragma unroll
            for (int c = 0; c < 4; c++) o_acc[a][c] *= corr;
            #pragma unroll
            for (int c = 0; c < 4; c++) Ps[(ty + 16 * a) * 64 + tx + 16 * c] = s[a][c];
        }
        __syncthreads();

        // O += P V
        #pragma unroll 8
        for (int j = 0; j < 64; j++) {
            float pv[4], vv[4];
            #pragma unroll
            for (int a = 0; a < 4; a++) pv[a] = Ps[(ty + 16 * a) * 64 + j];
            #pragma unroll
            for (int c = 0; c < 4; c++) vv[c] = Vs[j][tx + 16 * c];
            #pragma unroll
            for (int a = 0; a < 4; a++)
                #pragma unroll
                for (int c = 0; c < 4; c++)
                    o_acc[a][c] = fmaf(pv[a], vv[c], o_acc[a][c]);
        }
        __syncthreads();   // before Ps buffer becomes Kt again
    }

    #pragma unroll
    for (int a = 0; a < 4; a++) {
        const float inv = 1.f / l_r[a];
        float* Op = O + base + (size_t)(q0 + ty + 16 * a) * EMB;
        #pragma unroll
        for (int c = 0; c < 4; c++) Op[tx + 16 * c] = o_acc[a][c] * inv;
    }
}

// ---------------------------- launcher -------------------------------------
extern "C" void kernel_launch(void* const* d_in, const int* in_sizes, int n_in,
                              void* d_out, int out_size)
{
    const float* x    = (const float*)d_in[0];
    const int*   mask = (const int*)  d_in[1];
    const float* wq   = (const float*)d_in[2];
    const float* wk   = (const float*)d_in[3];
    const float* wv   = (const float*)d_in[4];
    const float* wo   = (const float*)d_in[5];
    const float* f1w  = (const float*)d_in[6];
    const float* f1b  = (const float*)d_in[7];
    const float* f2w  = (const float*)d_in[8];
    const float* f2b  = (const float*)d_in[9];
    const float* l1a  = (const float*)d_in[10];
    const float* l1b  = (const float*)d_in[11];
    const float* l2a  = (const float*)d_in[12];
    const float* l2b  = (const float*)d_in[13];
    float* out = (float*)d_out;

    float *xn, *q, *k, *v, *at, *h, *hn, *ac;
    cudaGetSymbolAddress((void**)&xn, g_xn);
    cudaGetSymbolAddress((void**)&q,  g_q);
    cudaGetSymbolAddress((void**)&k,  g_k);
    cudaGetSymbolAddress((void**)&v,  g_v);
    cudaGetSymbolAddress((void**)&at, g_at);
    cudaGetSymbolAddress((void**)&h,  g_h);
    cudaGetSymbolAddress((void**)&hn, g_hn);
    cudaGetSymbolAddress((void**)&ac, g_ac);

    // 1. ln1
    ln_kernel<<<MTOT, 256>>>(x, l1a, l1b, xn);
    // 2. QKV projections
    dim3 gEE(EMB / 128, MTOT / 128);
    sgemm_k<0,0,0><<<gEE, 256>>>(xn, wq, nullptr, nullptr, q, MTOT, EMB, EMB);
    sgemm_k<0,0,0><<<gEE, 256>>>(xn, wk, nullptr, nullptr, k, MTOT, EMB, EMB);
    sgemm_k<0,0,0><<<gEE, 256>>>(xn, wv, nullptr, nullptr, v, MTOT, EMB, EMB);
    // 3. attention
    attn_kernel<<<dim3(SQ / 64, NH, BATCH), 256>>>(q, k, v, mask, at);
    // 4. output projection + residual
    sgemm_k<0,0,1><<<gEE, 256>>>(at, wo, nullptr, x, h, MTOT, EMB, EMB);
    // 5. ln2
    ln_kernel<<<MTOT, 256>>>(h, l2a, l2b, hn);
    // 6. FFN
    sgemm_k<1,1,0><<<dim3(HID / 128, MTOT / 128), 256>>>(hn, f1w, f1b, nullptr, ac, MTOT, HID, EMB);
    sgemm_k<1,0,1><<<gEE, 256>>>(ac, f2w, f2b, h, out, MTOT, EMB, HID);
}

// round 3
// speedup vs baseline: 1.4773x; 1.4773x over previous
#include <cuda_runtime.h>
#include <cuda_bf16.h>
#include <cstdint>
#include <math.h>

#define EMB   1024
#define HID   4096
#define NH    16
#define DKH   64
#define SQ    2048
#define BATCH 2
#define MTOT  (BATCH*SQ)   // 4096 rows

// ---------------- scratch (device globals: allocation-free) ----------------
__device__ float g_xn[(size_t)MTOT*EMB];
__device__ float g_q [(size_t)MTOT*EMB];
__device__ float g_k [(size_t)MTOT*EMB];
__device__ float g_v [(size_t)MTOT*EMB];
__device__ float g_at[(size_t)MTOT*EMB];
__device__ float g_h [(size_t)MTOT*EMB];
__device__ float g_hn[(size_t)MTOT*EMB];
__device__ float g_ac[(size_t)MTOT*HID];

// ======================= portable tensor-core helpers ======================
__device__ __forceinline__ uint32_t s2u(const void* p) {
    uint32_t a;
    asm("{ .reg .u64 t; cvta.to.shared.u64 t, %1; cvt.u32.u64 %0, t; }"
        : "=r"(a) : "l"(p));
    return a;
}
__device__ __forceinline__ void ldsm4(uint32_t* r, uint32_t addr) {
    asm volatile("ldmatrix.sync.aligned.m8n8.x4.shared.b16 {%0,%1,%2,%3}, [%4];"
                 : "=r"(r[0]), "=r"(r[1]), "=r"(r[2]), "=r"(r[3]) : "r"(addr));
}
__device__ __forceinline__ void ldsm4t(uint32_t* r, uint32_t addr) {
    asm volatile("ldmatrix.sync.aligned.m8n8.x4.trans.shared.b16 {%0,%1,%2,%3}, [%4];"
                 : "=r"(r[0]), "=r"(r[1]), "=r"(r[2]), "=r"(r[3]) : "r"(addr));
}
__device__ __forceinline__ void mma16816(float* d, const uint32_t* a,
                                         const uint32_t b0, const uint32_t b1) {
    asm volatile(
        "mma.sync.aligned.m16n8k16.row.col.f32.bf16.bf16.f32 "
        "{%0,%1,%2,%3}, {%4,%5,%6,%7}, {%8,%9}, {%0,%1,%2,%3};"
        : "+f"(d[0]), "+f"(d[1]), "+f"(d[2]), "+f"(d[3])
        : "r"(a[0]), "r"(a[1]), "r"(a[2]), "r"(a[3]), "r"(b0), "r"(b1));
}
__device__ __forceinline__ uint32_t packbf(float a, float b) {
    __nv_bfloat16 ha = __float2bfloat16(a), hb = __float2bfloat16(b);
    return (uint32_t)__bfloat16_as_ushort(ha)
         | ((uint32_t)__bfloat16_as_ushort(hb) << 16);
}
__device__ __forceinline__ float bferr(float v) {
    return v - __bfloat162float(__float2bfloat16(v));
}

// ======================= split-bf16 mma.sync GEMM ==========================
// C[M,N] = A[M,K] @ B[K,N] (+bias)(+relu)(+res); fp32 in/out.
// 128x128 CTA tile, BK=32, 256 thr (8 warps, 2x4), warp tile 64x32.
#define ASTRIDE 40     // bf16 elems per A smem row (32 + 8 pad)
#define BSTRIDE 136    // bf16 elems per B smem row (128 + 8 pad)
#define AH_OFF  0
#define AL_OFF  (128*ASTRIDE)                 // 5120
#define BH_OFF  (2*128*ASTRIDE)               // 10240
#define BL_OFF  (2*128*ASTRIDE + 32*BSTRIDE)  // 14592
#define STAGE_E (2*128*ASTRIDE + 2*32*BSTRIDE) // 18944 bf16 elems
#define GSMEM   (2*STAGE_E*2)                 // 75776 bytes

template<int BIAS, int RELU, int RES>
__global__ void __launch_bounds__(256, 1) tc_gemm(
    const float* __restrict__ A, const float* __restrict__ Bw,
    const float* __restrict__ bias, const float* __restrict__ res,
    float* __restrict__ C, int M, int N, int K)
{
    extern __shared__ __nv_bfloat16 sm[];
    const uint32_t sbase = s2u(sm);
    const int tid = threadIdx.x, lane = tid & 31, wid = tid >> 5;
    const int wm = wid >> 2, wn = wid & 3;           // 2 x 4 warp grid
    const int bm = blockIdx.y * 128, bn = blockIdx.x * 128;

    // staging indices
    const int arow = tid >> 1, acol0 = (tid & 1) * 16;
    const int brow = tid >> 3, bcol0 = (tid & 7) * 16;

    float acc[4][4][4];
    #pragma unroll
    for (int i = 0; i < 4; i++)
        #pragma unroll
        for (int j = 0; j < 4; j++)
            #pragma unroll
            for (int e = 0; e < 4; e++) acc[i][j][e] = 0.f;

    float4 ra[4], rb[4];
    const int nch = K >> 5;

    // ldmatrix base offsets (in elems) that don't depend on stage
    const int a_r = wm * 64 + (lane & 15);
    const int a_c = (lane >> 4) * 8;
    const int b_r = (lane & 15);
    const int b_c = wn * 32 + (lane >> 4) * 8;

    auto LDG = [&](int c) {
        const int k0 = c * 32;
        const float4* Ap = (const float4*)(A + (size_t)(bm + arow) * K + k0 + acol0);
        const float4* Bp = (const float4*)(Bw + (size_t)(k0 + brow) * N + bn + bcol0);
        #pragma unroll
        for (int i = 0; i < 4; i++) { ra[i] = Ap[i]; rb[i] = Bp[i]; }
    };
    auto STS = [&](int s) {
        __nv_bfloat16* base = sm + s * STAGE_E;
        #pragma unroll
        for (int i = 0; i < 4; i++) {
            float4 v = ra[i];
            uint2 hi = make_uint2(packbf(v.x, v.y), packbf(v.z, v.w));
            uint2 lo = make_uint2(packbf(bferr(v.x), bferr(v.y)),
                                  packbf(bferr(v.z), bferr(v.w)));
            const int off = arow * ASTRIDE + acol0 + i * 4;
            *(uint2*)(base + AH_OFF + off) = hi;
            *(uint2*)(base + AL_OFF + off) = lo;
        }
        #pragma unroll
        for (int i = 0; i < 4; i++) {
            float4 v = rb[i];
            uint2 hi = make_uint2(packbf(v.x, v.y), packbf(v.z, v.w));
            uint2 lo = make_uint2(packbf(bferr(v.x), bferr(v.y)),
                                  packbf(bferr(v.z), bferr(v.w)));
            const int off = brow * BSTRIDE + bcol0 + i * 4;
            *(uint2*)(base + BH_OFF + off) = hi;
            *(uint2*)(base + BL_OFF + off) = lo;
        }
    };
    auto MMAS = [&](int s) {
        const uint32_t stg = sbase + s * (STAGE_E * 2);
        #pragma unroll
        for (int ks = 0; ks < 2; ks++) {
            uint32_t ah[4][4], al[4][4], bh[2][4], bl[2][4];
            #pragma unroll
            for (int mi = 0; mi < 4; mi++) {
                const uint32_t off =
                    ((a_r + mi * 16) * ASTRIDE + ks * 16 + a_c) * 2;
                ldsm4(ah[mi], stg + AH_OFF * 2 + off);
                ldsm4(al[mi], stg + AL_OFF * 2 + off);
            }
            #pragma unroll
            for (int np = 0; np < 2; np++) {
                const uint32_t off =
                    ((b_r + ks * 16) * BSTRIDE + b_c + np * 16) * 2;
                ldsm4t(bh[np], stg + BH_OFF * 2 + off);
                ldsm4t(bl[np], stg + BL_OFF * 2 + off);
            }
            #pragma unroll
            for (int mi = 0; mi < 4; mi++)
                #pragma unroll
                for (int ni = 0; ni < 4; ni++) {
                    const int np = ni >> 1, pr = (ni & 1) * 2;
                    mma16816(acc[mi][ni], ah[mi], bh[np][pr], bh[np][pr + 1]);
                    mma16816(acc[mi][ni], ah[mi], bl[np][pr], bl[np][pr + 1]);
                    mma16816(acc[mi][ni], al[mi], bh[np][pr], bh[np][pr + 1]);
                }
        }
    };

    LDG(0);
    STS(0);
    __syncthreads();
    for (int c = 0; c < nch; c++) {
        const bool more = (c + 1 < nch);
        if (more) LDG(c + 1);
        MMAS(c & 1);
        if (more) STS((c + 1) & 1);
        __syncthreads();
    }

    // ---- epilogue: frag -> gmem with fused bias/relu/residual ----
    const int g = lane >> 2, t4 = lane & 3;
    #pragma unroll
    for (int mi = 0; mi < 4; mi++) {
        const int r0 = bm + wm * 64 + mi * 16 + g;
        #pragma unroll
        for (int half = 0; half < 2; half++) {
            const int row = r0 + half * 8;
            float* Cp = C + (size_t)row * N;
            const float* Rp = RES ? (res + (size_t)row * N) : (const float*)nullptr;
            #pragma unroll
            for (int ni = 0; ni < 4; ni++) {
                const int col = bn + wn * 32 + ni * 8 + t4 * 2;
                float v0 = acc[mi][ni][half * 2 + 0];
                float v1 = acc[mi][ni][half * 2 + 1];
                if (BIAS) { v0 += bias[col]; v1 += bias[col + 1]; }
                if (RELU) { v0 = fmaxf(v0, 0.f); v1 = fmaxf(v1, 0.f); }
                if (RES)  { v0 += Rp[col]; v1 += Rp[col + 1]; }
                *(float2*)(Cp + col) = make_float2(v0, v1);
            }
        }
    }
}

// ---------------- LayerNorm (faithful: Bessel var, /(std+eps)) -------------
__global__ void ln_kernel(const float* __restrict__ in,
                          const float* __restrict__ alpha,
                          const float* __restrict__ beta,
                          float* __restrict__ out)
{
    __shared__ float row[EMB];
    __shared__ float red[8];
    const int r   = blockIdx.x;
    const int tid = threadIdx.x;
    const float* p = in + (size_t)r * EMB;

    float s = 0.f;
    #pragma unroll
    for (int i = tid; i < EMB; i += 256) { float v = p[i]; row[i] = v; s += v; }
    #pragma unroll
    for (int o = 16; o; o >>= 1) s += __shfl_xor_sync(0xffffffffu, s, o);
    if ((tid & 31) == 0) red[tid >> 5] = s;
    __syncthreads();
    if (tid < 8) {
        float t = red[tid];
        #pragma unroll
        for (int o = 4; o; o >>= 1) t += __shfl_xor_sync(0xffu, t, o);
        if (tid == 0) red[0] = t;
    }
    __syncthreads();
    const float mean = red[0] * (1.f / EMB);

    float s2 = 0.f;
    #pragma unroll
    for (int i = tid; i < EMB; i += 256) { float d = row[i] - mean; s2 += d * d; }
    #pragma unroll
    for (int o = 16; o; o >>= 1) s2 += __shfl_xor_sync(0xffffffffu, s2, o);
    __syncthreads();
    if ((tid & 31) == 0) red[tid >> 5] = s2;
    __syncthreads();
    if (tid < 8) {
        float t = red[tid];
        #pragma unroll
        for (int o = 4; o; o >>= 1) t += __shfl_xor_sync(0xffu, t, o);
        if (tid == 0) red[0] = t;
    }
    __syncthreads();
    const float var   = red[0] * (1.f / (EMB - 1));
    const float scale = alpha[0] / (sqrtf(var) + 1e-6f);
    const float bias  = beta[0];

    float* op = out + (size_t)r * EMB;
    #pragma unroll
    for (int i = tid; i < EMB; i += 256) op[i] = (row[i] - mean) * scale + bias;
}

// ---------------- flash attention, fp32, 64-query tiles --------------------
__global__ void __launch_bounds__(256, 2) attn_kernel(
    const float* __restrict__ Q, const float* __restrict__ Kg,
    const float* __restrict__ Vg, const int* __restrict__ mask,
    float* __restrict__ O)
{
    __shared__ float Qt[64][64];   // [d][q]  transposed
    __shared__ float KP[64 * 64];  // Kt [d][j]  aliased with Ps [i][j]
    __shared__ float Vs[64][64];   // [j][d]
    const int b  = blockIdx.z, h = blockIdx.y;
    const int q0 = blockIdx.x * 64;
    const int tid = threadIdx.x;
    const int tx = tid & 15, ty = tid >> 4;
    const size_t base = (size_t)b * SQ * EMB + (size_t)h * DKH;

    {
        const int j = tid & 63, d4 = tid >> 6;
        #pragma unroll
        for (int it = 0; it < 4; it++) {
            const int d = (d4 + it * 4) * 4;
            float4 v = *(const float4*)(Q + base + (size_t)(q0 + j) * EMB + d);
            Qt[d + 0][j] = v.x; Qt[d + 1][j] = v.y;
            Qt[d + 2][j] = v.z; Qt[d + 3][j] = v.w;
        }
    }

    float m_r[4], l_r[4], o_acc[4][4];
    #pragma unroll
    for (int a = 0; a < 4; a++) {
        m_r[a] = -1e30f; l_r[a] = 0.f;
        #pragma unroll
        for (int c = 0; c < 4; c++) o_acc[a][c] = 0.f;
    }

    float* Kt = KP;
    float* Ps = KP;
    const float scale = 0.125f;

    for (int j0 = 0; j0 < SQ; j0 += 64) {
        {
            const int j = tid & 63, d4 = tid >> 6;
            #pragma unroll
            for (int it = 0; it < 4; it++) {
                const int d = (d4 + it * 4) * 4;
                float4 v = *(const float4*)(Kg + base + (size_t)(j0 + j) * EMB + d);
                Kt[(d + 0) * 64 + j] = v.x; Kt[(d + 1) * 64 + j] = v.y;
                Kt[(d + 2) * 64 + j] = v.z; Kt[(d + 3) * 64 + j] = v.w;
            }
            const int r = tid >> 4, c4 = (tid & 15) * 4;
            #pragma unroll
            for (int it = 0; it < 4; it++) {
                const int j2 = r + it * 16;
                *(float4*)&Vs[j2][c4] =
                    *(const float4*)(Vg + base + (size_t)(j0 + j2) * EMB + c4);
            }
        }
        __syncthreads();

        float s[4][4];
        #pragma unroll
        for (int a = 0; a < 4; a++)
            #pragma unroll
            for (int c = 0; c < 4; c++) s[a][c] = 0.f;
        #pragma unroll 8
        for (int d = 0; d < 64; d++) {
            float qv[4], kv[4];
            #pragma unroll
            for (int a = 0; a < 4; a++) qv[a] = Qt[d][ty + 16 * a];
            #pragma unroll
            for (int c = 0; c < 4; c++) kv[c] = Kt[d * 64 + tx + 16 * c];
            #pragma unroll
            for (int a = 0; a < 4; a++)
                #pragma unroll
                for (int c = 0; c < 4; c++)
                    s[a][c] = fmaf(qv[a], kv[c], s[a][c]);
        }
        int mk[4];
        #pragma unroll
        for (int c = 0; c < 4; c++) mk[c] = mask[b * SQ + j0 + tx + 16 * c];
        #pragma unroll
        for (int a = 0; a < 4; a++)
            #pragma unroll
            for (int c = 0; c < 4; c++)
                s[a][c] = (mk[c] == 0) ? -1e30f : s[a][c] * scale;

        __syncthreads();

        #pragma unroll
        for (int a = 0; a < 4; a++) {
            float tm = fmaxf(fmaxf(s[a][0], s[a][1]), fmaxf(s[a][2], s[a][3]));
            #pragma unroll
            for (int o = 8; o; o >>= 1) tm = fmaxf(tm, __shfl_xor_sync(0xffffffffu, tm, o));
            const float mn   = fmaxf(m_r[a], tm);
            const float corr = __expf(m_r[a] - mn);
            float ts = 0.f;
            #pragma unroll
            for (int c = 0; c < 4; c++) { float p = __expf(s[a][c] - mn); s[a][c] = p; ts += p; }
            #pragma unroll
            for (int o = 8; o; o >>= 1) ts += __shfl_xor_sync(0xffffffffu, ts, o);
            l_r[a] = l_r[a] * corr + ts;
            m_r[a] = mn;
            #pragma unroll
            for (int c = 0; c < 4; c++) o_acc[a][c] *= corr;
            #pragma unroll
            for (int c = 0; c < 4; c++) Ps[(ty + 16 * a) * 64 + tx + 16 * c] = s[a][c];
        }
        __syncthreads();

        #pragma unroll 8
        for (int j = 0; j < 64; j++) {
            float pv[4], vv[4];
            #pragma unroll
            for (int a = 0; a < 4; a++) pv[a] = Ps[(ty + 16 * a) * 64 + j];
            #pragma unroll
            for (int c = 0; c < 4; c++) vv[c] = Vs[j][tx + 16 * c];
            #pragma unroll
            for (int a = 0; a < 4; a++)
                #pragma unroll
                for (int c = 0; c < 4; c++)
                    o_acc[a][c] = fmaf(pv[a], vv[c], o_acc[a][c]);
        }
        __syncthreads();
    }

    #pragma unroll
    for (int a = 0; a < 4; a++) {
        const float inv = 1.f / l_r[a];
        float* Op = O + base + (size_t)(q0 + ty + 16 * a) * EMB;
        #pragma unroll
        for (int c = 0; c < 4; c++) Op[tx + 16 * c] = o_acc[a][c] * inv;
    }
}

// ---------------------------- launcher -------------------------------------
extern "C" void kernel_launch(void* const* d_in, const int* in_sizes, int n_in,
                              void* d_out, int out_size)
{
    const float* x    = (const float*)d_in[0];
    const int*   mask = (const int*)  d_in[1];
    const float* wq   = (const float*)d_in[2];
    const float* wk   = (const float*)d_in[3];
    const float* wv   = (const float*)d_in[4];
    const float* wo   = (const float*)d_in[5];
    const float* f1w  = (const float*)d_in[6];
    const float* f1b  = (const float*)d_in[7];
    const float* f2w  = (const float*)d_in[8];
    const float* f2b  = (const float*)d_in[9];
    const float* l1a  = (const float*)d_in[10];
    const float* l1b  = (const float*)d_in[11];
    const float* l2a  = (const float*)d_in[12];
    const float* l2b  = (const float*)d_in[13];
    float* out = (float*)d_out;

    float *xn, *q, *k, *v, *at, *h, *hn, *ac;
    cudaGetSymbolAddress((void**)&xn, g_xn);
    cudaGetSymbolAddress((void**)&q,  g_q);
    cudaGetSymbolAddress((void**)&k,  g_k);
    cudaGetSymbolAddress((void**)&v,  g_v);
    cudaGetSymbolAddress((void**)&at, g_at);
    cudaGetSymbolAddress((void**)&h,  g_h);
    cudaGetSymbolAddress((void**)&hn, g_hn);
    cudaGetSymbolAddress((void**)&ac, g_ac);

    cudaFuncSetAttribute(tc_gemm<0,0,0>, cudaFuncAttributeMaxDynamicSharedMemorySize, GSMEM);
    cudaFuncSetAttribute(tc_gemm<0,0,1>, cudaFuncAttributeMaxDynamicSharedMemorySize, GSMEM);
    cudaFuncSetAttribute(tc_gemm<1,1,0>, cudaFuncAttributeMaxDynamicSharedMemorySize, GSMEM);
    cudaFuncSetAttribute(tc_gemm<1,0,1>, cudaFuncAttributeMaxDynamicSharedMemorySize, GSMEM);

    // 1. ln1
    ln_kernel<<<MTOT, 256>>>(x, l1a, l1b, xn);
    // 2. QKV projections
    dim3 gEE(EMB / 128, MTOT / 128);
    tc_gemm<0,0,0><<<gEE, 256, GSMEM>>>(xn, wq, nullptr, nullptr, q, MTOT, EMB, EMB);
    tc_gemm<0,0,0><<<gEE, 256, GSMEM>>>(xn, wk, nullptr, nullptr, k, MTOT, EMB, EMB);
    tc_gemm<0,0,0><<<gEE, 256, GSMEM>>>(xn, wv, nullptr, nullptr, v, MTOT, EMB, EMB);
    // 3. attention
    attn_kernel<<<dim3(SQ / 64, NH, BATCH), 256>>>(q, k, v, mask, at);
    // 4. output projection + residual
    tc_gemm<0,0,1><<<gEE, 256, GSMEM>>>(at, wo, nullptr, x, h, MTOT, EMB, EMB);
    // 5. ln2
    ln_kernel<<<MTOT, 256>>>(h, l2a, l2b, hn);
    // 6. FFN
    tc_gemm<1,1,0><<<dim3(HID / 128, MTOT / 128), 256, GSMEM>>>(hn, f1w, f1b, nullptr, ac, MTOT, HID, EMB);
    tc_gemm<1,0,1><<<gEE, 256, GSMEM>>>(ac, f2w, f2b, h, out, MTOT, EMB, HID);
}

// round 5
// speedup vs baseline: 2.0623x; 1.3959x over previous
#include <cuda_runtime.h>
#include <cuda_bf16.h>
#include <cstdint>
#include <math.h>

#define EMB   1024
#define HID   4096
#define NH    16
#define DKH   64
#define SQ    2048
#define BATCH 2
#define MTOT  (BATCH*SQ)   // 4096 rows

// ---------------- scratch (device globals: allocation-free) ----------------
__device__ float g_xn[(size_t)MTOT*EMB];
__device__ float g_q [(size_t)MTOT*EMB];
__device__ float g_k [(size_t)MTOT*EMB];
__device__ float g_v [(size_t)MTOT*EMB];
__device__ float g_at[(size_t)MTOT*EMB];
__device__ float g_h [(size_t)MTOT*EMB];
__device__ float g_hn[(size_t)MTOT*EMB];
__device__ float g_ac[(size_t)MTOT*HID];

// ======================= portable tensor-core helpers ======================
__device__ __forceinline__ uint32_t s2u(const void* p) {
    uint32_t a;
    asm("{ .reg .u64 t; cvta.to.shared.u64 t, %1; cvt.u32.u64 %0, t; }"
        : "=r"(a) : "l"(p));
    return a;
}
__device__ __forceinline__ void ldsm4(uint32_t* r, uint32_t addr) {
    asm volatile("ldmatrix.sync.aligned.m8n8.x4.shared.b16 {%0,%1,%2,%3}, [%4];"
                 : "=r"(r[0]), "=r"(r[1]), "=r"(r[2]), "=r"(r[3]) : "r"(addr));
}
__device__ __forceinline__ void ldsm4t(uint32_t* r, uint32_t addr) {
    asm volatile("ldmatrix.sync.aligned.m8n8.x4.trans.shared.b16 {%0,%1,%2,%3}, [%4];"
                 : "=r"(r[0]), "=r"(r[1]), "=r"(r[2]), "=r"(r[3]) : "r"(addr));
}
__device__ __forceinline__ void mma16816(float* d, const uint32_t* a,
                                         const uint32_t b0, const uint32_t b1) {
    asm volatile(
        "mma.sync.aligned.m16n8k16.row.col.f32.bf16.bf16.f32 "
        "{%0,%1,%2,%3}, {%4,%5,%6,%7}, {%8,%9}, {%0,%1,%2,%3};"
        : "+f"(d[0]), "+f"(d[1]), "+f"(d[2]), "+f"(d[3])
        : "r"(a[0]), "r"(a[1]), "r"(a[2]), "r"(a[3]), "r"(b0), "r"(b1));
}
__device__ __forceinline__ uint32_t packbf(float a, float b) {
    __nv_bfloat16 ha = __float2bfloat16(a), hb = __float2bfloat16(b);
    return (uint32_t)__bfloat16_as_ushort(ha)
         | ((uint32_t)__bfloat16_as_ushort(hb) << 16);
}
__device__ __forceinline__ float bferr(float v) {
    return v - __bfloat162float(__float2bfloat16(v));
}

// ======================= split-bf16 mma.sync GEMM ==========================
// 128x128 CTA tile, BK=32, 512 thr (16 warps, 4x4), warp tile 32x32.
#define ASTRIDE 40     // bf16 elems per A smem row (32 + 8 pad)
#define BSTRIDE 136    // bf16 elems per B smem row (128 + 8 pad)
#define AH_OFF  0
#define AL_OFF  (128*ASTRIDE)
#define BH_OFF  (2*128*ASTRIDE)
#define BL_OFF  (2*128*ASTRIDE + 32*BSTRIDE)
#define STAGE_E (2*128*ASTRIDE + 2*32*BSTRIDE)
#define GSMEM   (2*STAGE_E*2)

template<int BIAS, int RELU, int RES>
__global__ void __launch_bounds__(512, 1) tc_gemm(
    const float* __restrict__ A, const float* __restrict__ Bw,
    const float* __restrict__ bias, const float* __restrict__ res,
    float* __restrict__ C, int M, int N, int K)
{
    extern __shared__ __nv_bfloat16 sm[];
    const uint32_t sbase = s2u(sm);
    const int tid = threadIdx.x, lane = tid & 31, wid = tid >> 5;
    const int wm = wid >> 2, wn = wid & 3;           // 4 x 4 warp grid
    const int bm = blockIdx.y * 128, bn = blockIdx.x * 128;

    // staging indices
    const int arow = tid >> 2, acol0 = (tid & 3) * 8;
    const int brow = tid >> 4, bcol0 = (tid & 15) * 8;

    float acc[2][4][4];
    #pragma unroll
    for (int i = 0; i < 2; i++)
        #pragma unroll
        for (int j = 0; j < 4; j++)
            #pragma unroll
            for (int e = 0; e < 4; e++) acc[i][j][e] = 0.f;

    float4 ra[2], rb[2];
    const int nch = K >> 5;

    const int a_r = wm * 32 + (lane & 15);
    const int a_c = (lane >> 4) * 8;
    const int b_r = (lane & 15);
    const int b_c = wn * 32 + (lane >> 4) * 8;

    auto LDG = [&](int c) {
        const int k0 = c * 32;
        const float4* Ap = (const float4*)(A + (size_t)(bm + arow) * K + k0 + acol0);
        const float4* Bp = (const float4*)(Bw + (size_t)(k0 + brow) * N + bn + bcol0);
        #pragma unroll
        for (int i = 0; i < 2; i++) { ra[i] = Ap[i]; rb[i] = Bp[i]; }
    };
    auto STS = [&](int s) {
        __nv_bfloat16* base = sm + s * STAGE_E;
        #pragma unroll
        for (int i = 0; i < 2; i++) {
            float4 v = ra[i];
            uint2 hi = make_uint2(packbf(v.x, v.y), packbf(v.z, v.w));
            uint2 lo = make_uint2(packbf(bferr(v.x), bferr(v.y)),
                                  packbf(bferr(v.z), bferr(v.w)));
            const int off = arow * ASTRIDE + acol0 + i * 4;
            *(uint2*)(base + AH_OFF + off) = hi;
            *(uint2*)(base + AL_OFF + off) = lo;
        }
        #pragma unroll
        for (int i = 0; i < 2; i++) {
            float4 v = rb[i];
            uint2 hi = make_uint2(packbf(v.x, v.y), packbf(v.z, v.w));
            uint2 lo = make_uint2(packbf(bferr(v.x), bferr(v.y)),
                                  packbf(bferr(v.z), bferr(v.w)));
            const int off = brow * BSTRIDE + bcol0 + i * 4;
            *(uint2*)(base + BH_OFF + off) = hi;
            *(uint2*)(base + BL_OFF + off) = lo;
        }
    };
    auto MMAS = [&](int s) {
        const uint32_t stg = sbase + s * (STAGE_E * 2);
        #pragma unroll
        for (int ks = 0; ks < 2; ks++) {
            uint32_t ah[2][4], al[2][4], bh[2][4], bl[2][4];
            #pragma unroll
            for (int mi = 0; mi < 2; mi++) {
                const uint32_t off =
                    ((a_r + mi * 16) * ASTRIDE + ks * 16 + a_c) * 2;
                ldsm4(ah[mi], stg + AH_OFF * 2 + off);
                ldsm4(al[mi], stg + AL_OFF * 2 + off);
            }
            #pragma unroll
            for (int np = 0; np < 2; np++) {
                const uint32_t off =
                    ((b_r + ks * 16) * BSTRIDE + b_c + np * 16) * 2;
                ldsm4t(bh[np], stg + BH_OFF * 2 + off);
                ldsm4t(bl[np], stg + BL_OFF * 2 + off);
            }
            #pragma unroll
            for (int mi = 0; mi < 2; mi++)
                #pragma unroll
                for (int ni = 0; ni < 4; ni++) {
                    const int np = ni >> 1, pr = (ni & 1) * 2;
                    mma16816(acc[mi][ni], ah[mi], bh[np][pr], bh[np][pr + 1]);
                    mma16816(acc[mi][ni], ah[mi], bl[np][pr], bl[np][pr + 1]);
                    mma16816(acc[mi][ni], al[mi], bh[np][pr], bh[np][pr + 1]);
                }
        }
    };

    LDG(0);
    STS(0);
    __syncthreads();
    for (int c = 0; c < nch; c++) {
        const bool more = (c + 1 < nch);
        if (more) LDG(c + 1);
        MMAS(c & 1);
        if (more) STS((c + 1) & 1);
        __syncthreads();
    }

    const int g = lane >> 2, t4 = lane & 3;
    #pragma unroll
    for (int mi = 0; mi < 2; mi++) {
        const int r0 = bm + wm * 32 + mi * 16 + g;
        #pragma unroll
        for (int half = 0; half < 2; half++) {
            const int row = r0 + half * 8;
            float* Cp = C + (size_t)row * N;
            const float* Rp = RES ? (res + (size_t)row * N) : (const float*)nullptr;
            #pragma unroll
            for (int ni = 0; ni < 4; ni++) {
                const int col = bn + wn * 32 + ni * 8 + t4 * 2;
                float v0 = acc[mi][ni][half * 2 + 0];
                float v1 = acc[mi][ni][half * 2 + 1];
                if (BIAS) { v0 += bias[col]; v1 += bias[col + 1]; }
                if (RELU) { v0 = fmaxf(v0, 0.f); v1 = fmaxf(v1, 0.f); }
                if (RES)  { v0 += Rp[col]; v1 += Rp[col + 1]; }
                *(float2*)(Cp + col) = make_float2(v0, v1);
            }
        }
    }
}

// ---------------- LayerNorm (faithful: Bessel var, /(std+eps)) -------------
__global__ void ln_kernel(const float* __restrict__ in,
                          const float* __restrict__ alpha,
                          const float* __restrict__ beta,
                          float* __restrict__ out)
{
    __shared__ float row[EMB];
    __shared__ float red[8];
    const int r   = blockIdx.x;
    const int tid = threadIdx.x;
    const float* p = in + (size_t)r * EMB;

    float s = 0.f;
    #pragma unroll
    for (int i = tid; i < EMB; i += 256) { float v = p[i]; row[i] = v; s += v; }
    #pragma unroll
    for (int o = 16; o; o >>= 1) s += __shfl_xor_sync(0xffffffffu, s, o);
    if ((tid & 31) == 0) red[tid >> 5] = s;
    __syncthreads();
    if (tid < 8) {
        float t = red[tid];
        #pragma unroll
        for (int o = 4; o; o >>= 1) t += __shfl_xor_sync(0xffu, t, o);
        if (tid == 0) red[0] = t;
    }
    __syncthreads();
    const float mean = red[0] * (1.f / EMB);

    float s2 = 0.f;
    #pragma unroll
    for (int i = tid; i < EMB; i += 256) { float d = row[i] - mean; s2 += d * d; }
    #pragma unroll
    for (int o = 16; o; o >>= 1) s2 += __shfl_xor_sync(0xffffffffu, s2, o);
    __syncthreads();
    if ((tid & 31) == 0) red[tid >> 5] = s2;
    __syncthreads();
    if (tid < 8) {
        float t = red[tid];
        #pragma unroll
        for (int o = 4; o; o >>= 1) t += __shfl_xor_sync(0xffu, t, o);
        if (tid == 0) red[0] = t;
    }
    __syncthreads();
    const float var   = red[0] * (1.f / (EMB - 1));
    const float scale = alpha[0] / (sqrtf(var) + 1e-6f);
    const float bias  = beta[0];

    float* op = out + (size_t)r * EMB;
    #pragma unroll
    for (int i = tid; i < EMB; i += 256) op[i] = (row[i] - mean) * scale + bias;
}

// =============== tensor-core flash attention (split bf16) ==================
// CTA: 64 queries of one (b,h). 256 thr, 8 warps = 4 m-warps x 2 n-warps.
// smem layout (bf16 stride 72 unless noted):
#define TSTR   72
#define KTHI_O 0
#define KTLO_O 9216
#define VHI_O  18432
#define VLO_O  27648
#define PHI_O  36864   // aliases Q hi (Q frags preloaded to regs)
#define PLO_O  46080
#define REDM_O 55296   // float[2][64]
#define REDL_O 55808   // float[2][64]
#define ASMEM  56320

__global__ void __launch_bounds__(256, 2) attn_tc(
    const float* __restrict__ Q, const float* __restrict__ Kg,
    const float* __restrict__ Vg, const int* __restrict__ mask,
    float* __restrict__ O)
{
    extern __shared__ char asm_[];
    const uint32_t sb = s2u(asm_);
    __nv_bfloat16* smb = (__nv_bfloat16*)asm_;
    float* redm = (float*)(asm_ + REDM_O);
    float* redl = (float*)(asm_ + REDL_O);

    const int b  = blockIdx.z, h = blockIdx.y;
    const int q0 = blockIdx.x * 64;
    const int tid = threadIdx.x, lane = tid & 31, wid = tid >> 5;
    const int wm = wid >> 1, wn = wid & 1;          // 4 x 2 warp grid
    const int g = lane >> 2, t4 = lane & 3;
    const size_t base = (size_t)b * SQ * EMB + (size_t)h * DKH;

    // ---- stage Q (scaled by 1/8) into PHI/PLO region, natural [q][dk] ----
    {
        const int qr = tid >> 2, c0 = (tid & 3) * 16;
        const float4* Qp = (const float4*)(Q + base + (size_t)(q0 + qr) * EMB + c0);
        #pragma unroll
        for (int i = 0; i < 4; i++) {
            float4 v = Qp[i];
            v.x *= 0.125f; v.y *= 0.125f; v.z *= 0.125f; v.w *= 0.125f;
            uint2 hi = make_uint2(packbf(v.x, v.y), packbf(v.z, v.w));
            uint2 lo = make_uint2(packbf(bferr(v.x), bferr(v.y)),
                                  packbf(bferr(v.z), bferr(v.w)));
            const int off = qr * TSTR + c0 + i * 4;
            *(uint2*)(smb + PHI_O / 2 + off) = hi;
            *(uint2*)(smb + PLO_O / 2 + off) = lo;
        }
    }
    __syncthreads();

    // ---- preload Q fragments (rows = this warp's m16) ----
    uint32_t qh[4][4], ql[4][4];
    {
        const int a_r = wm * 16 + (lane & 15);
        const int a_c = (lane >> 4) * 8;
        #pragma unroll
        for (int ks = 0; ks < 4; ks++) {
            const uint32_t off = (a_r * TSTR + ks * 16 + a_c) * 2;
            ldsm4(qh[ks], sb + PHI_O + off);
            ldsm4(ql[ks], sb + PLO_O + off);
        }
    }

    float m_r[2] = {-1e30f, -1e30f}, l_r[2] = {0.f, 0.f};
    float acc_o[4][4];
    #pragma unroll
    for (int ni = 0; ni < 4; ni++)
        #pragma unroll
        for (int e = 0; e < 4; e++) acc_o[ni][e] = 0.f;

    for (int j0 = 0; j0 < SQ; j0 += 64) {
        __syncthreads();   // prev tile's smem reads complete
        // ---- stage K transposed [dk][key] hi/lo ----
        {
            const int jj = (tid & 31) * 2, d0 = (tid >> 5) * 4;
            #pragma unroll
            for (int r = 0; r < 2; r++) {
                const int d = d0 + r * 32;
                float4 a = *(const float4*)(Kg + base + (size_t)(j0 + jj) * EMB + d);
                float4 c = *(const float4*)(Kg + base + (size_t)(j0 + jj + 1) * EMB + d);
                const float av[4] = {a.x, a.y, a.z, a.w};
                const float cv[4] = {c.x, c.y, c.z, c.w};
                #pragma unroll
                for (int i = 0; i < 4; i++) {
                    const int off = (d + i) * TSTR + jj;
                    *(uint32_t*)(smb + KTHI_O / 2 + off) = packbf(av[i], cv[i]);
                    *(uint32_t*)(smb + KTLO_O / 2 + off) =
                        packbf(bferr(av[i]), bferr(cv[i]));
                }
            }
        }
        // ---- stage V natural [key][dk] hi/lo ----
        {
            const int vr = tid >> 2, c0 = (tid & 3) * 16;
            const float4* Vp = (const float4*)(Vg + base + (size_t)(j0 + vr) * EMB + c0);
            #pragma unroll
            for (int i = 0; i < 4; i++) {
                float4 v = Vp[i];
                uint2 hi = make_uint2(packbf(v.x, v.y), packbf(v.z, v.w));
                uint2 lo = make_uint2(packbf(bferr(v.x), bferr(v.y)),
                                      packbf(bferr(v.z), bferr(v.w)));
                const int off = vr * TSTR + c0 + i * 4;
                *(uint2*)(smb + VHI_O / 2 + off) = hi;
                *(uint2*)(smb + VLO_O / 2 + off) = lo;
            }
        }
        __syncthreads();

        // ---- S = (Q/8) @ K^T  (3-pass split) ----
        float s[4][4];
        #pragma unroll
        for (int ni = 0; ni < 4; ni++)
            #pragma unroll
            for (int e = 0; e < 4; e++) s[ni][e] = 0.f;
        #pragma unroll
        for (int ks = 0; ks < 4; ks++) {
            uint32_t bh[2][4], bl[2][4];
            #pragma unroll
            for (int np = 0; np < 2; np++) {
                const uint32_t off =
                    (((lane & 15) + ks * 16) * TSTR
                     + wn * 32 + np * 16 + (lane >> 4) * 8) * 2;
                ldsm4t(bh[np], sb + KTHI_O + off);
                ldsm4t(bl[np], sb + KTLO_O + off);
            }
            #pragma unroll
            for (int ni = 0; ni < 4; ni++) {
                const int np = ni >> 1, pr = (ni & 1) * 2;
                mma16816(s[ni], qh[ks], bh[np][pr], bh[np][pr + 1]);
                mma16816(s[ni], qh[ks], bl[np][pr], bl[np][pr + 1]);
                mma16816(s[ni], ql[ks], bh[np][pr], bh[np][pr + 1]);
            }
        }

        // ---- mask ----
        #pragma unroll
        for (int ni = 0; ni < 4; ni++) {
            const int c = j0 + wn * 32 + ni * 8 + t4 * 2;
            int2 mk = *(const int2*)(mask + b * SQ + c);
            if (mk.x == 0) { s[ni][0] = -1e30f; s[ni][2] = -1e30f; }
            if (mk.y == 0) { s[ni][1] = -1e30f; s[ni][3] = -1e30f; }
        }

        // ---- online softmax ----
        float lmax[2] = {-1e30f, -1e30f};
        #pragma unroll
        for (int ni = 0; ni < 4; ni++) {
            lmax[0] = fmaxf(lmax[0], fmaxf(s[ni][0], s[ni][1]));
            lmax[1] = fmaxf(lmax[1], fmaxf(s[ni][2], s[ni][3]));
        }
        #pragma unroll
        for (int o = 1; o <= 2; o <<= 1) {
            lmax[0] = fmaxf(lmax[0], __shfl_xor_sync(0xffffffffu, lmax[0], o));
            lmax[1] = fmaxf(lmax[1], __shfl_xor_sync(0xffffffffu, lmax[1], o));
        }
        if (t4 == 0) {
            redm[wn * 64 + wm * 16 + g] = lmax[0];
            redm[wn * 64 + wm * 16 + g + 8] = lmax[1];
        }
        __syncthreads();
        float mn[2], corr[2];
        #pragma unroll
        for (int r = 0; r < 2; r++) {
            const int row = wm * 16 + g + r * 8;
            const float tm = fmaxf(redm[row], redm[64 + row]);
            mn[r] = fmaxf(m_r[r], tm);
            corr[r] = __expf(m_r[r] - mn[r]);
            m_r[r] = mn[r];
        }
        float lsum[2] = {0.f, 0.f};
        #pragma unroll
        for (int ni = 0; ni < 4; ni++) {
            float p0 = __expf(s[ni][0] - mn[0]);
            float p1 = __expf(s[ni][1] - mn[0]);
            float p2 = __expf(s[ni][2] - mn[1]);
            float p3 = __expf(s[ni][3] - mn[1]);
            lsum[0] += p0 + p1; lsum[1] += p2 + p3;
            // store P hi/lo to smem (cols = wn*32 + ni*8 + 2*t4, rows g/g+8)
            const int colb = wn * 32 + ni * 8 + t4 * 2;
            const int off0 = (wm * 16 + g) * TSTR + colb;
            const int off8 = (wm * 16 + g + 8) * TSTR + colb;
            *(uint32_t*)(smb + PHI_O / 2 + off0) = packbf(p0, p1);
            *(uint32_t*)(smb + PLO_O / 2 + off0) = packbf(bferr(p0), bferr(p1));
            *(uint32_t*)(smb + PHI_O / 2 + off8) = packbf(p2, p3);
            *(uint32_t*)(smb + PLO_O / 2 + off8) = packbf(bferr(p2), bferr(p3));
        }
        #pragma unroll
        for (int o = 1; o <= 2; o <<= 1) {
            lsum[0] += __shfl_xor_sync(0xffffffffu, lsum[0], o);
            lsum[1] += __shfl_xor_sync(0xffffffffu, lsum[1], o);
        }
        if (t4 == 0) {
            redl[wn * 64 + wm * 16 + g] = lsum[0];
            redl[wn * 64 + wm * 16 + g + 8] = lsum[1];
        }
        __syncthreads();
        #pragma unroll
        for (int r = 0; r < 2; r++) {
            const int row = wm * 16 + g + r * 8;
            l_r[r] = l_r[r] * corr[r] + redl[row] + redl[64 + row];
        }
        #pragma unroll
        for (int ni = 0; ni < 4; ni++) {
            acc_o[ni][0] *= corr[0]; acc_o[ni][1] *= corr[0];
            acc_o[ni][2] *= corr[1]; acc_o[ni][3] *= corr[1];
        }

        // ---- O += P @ V  (3-pass split) ----
        #pragma unroll
        for (int ks = 0; ks < 4; ks++) {
            uint32_t ph[4], pl[4], vh[2][4], vl[2][4];
            {
                const uint32_t off =
                    ((wm * 16 + (lane & 15)) * TSTR + ks * 16 + (lane >> 4) * 8) * 2;
                ldsm4(ph, sb + PHI_O + off);
                ldsm4(pl, sb + PLO_O + off);
            }
            #pragma unroll
            for (int np = 0; np < 2; np++) {
                const uint32_t off =
                    (((lane & 15) + ks * 16) * TSTR
                     + wn * 32 + np * 16 + (lane >> 4) * 8) * 2;
                ldsm4t(vh[np], sb + VHI_O + off);
                ldsm4t(vl[np], sb + VLO_O + off);
            }
            #pragma unroll
            for (int ni = 0; ni < 4; ni++) {
                const int np = ni >> 1, pr = (ni & 1) * 2;
                mma16816(acc_o[ni], ph, vh[np][pr], vh[np][pr + 1]);
                mma16816(acc_o[ni], ph, vl[np][pr], vl[np][pr + 1]);
                mma16816(acc_o[ni], pl, vh[np][pr], vh[np][pr + 1]);
            }
        }
    }

    // ---- write O / l ----
    const float inv0 = 1.f / l_r[0], inv1 = 1.f / l_r[1];
    #pragma unroll
    for (int r = 0; r < 2; r++) {
        const int qrow = q0 + wm * 16 + g + r * 8;
        float* Op = O + (size_t)(b * SQ + qrow) * EMB + h * DKH;
        const float inv = r ? inv1 : inv0;
        #pragma unroll
        for (int ni = 0; ni < 4; ni++) {
            const int col = wn * 32 + ni * 8 + t4 * 2;
            *(float2*)(Op + col) = make_float2(acc_o[ni][r * 2 + 0] * inv,
                                               acc_o[ni][r * 2 + 1] * inv);
        }
    }
}

// ---------------------------- launcher -------------------------------------
extern "C" void kernel_launch(void* const* d_in, const int* in_sizes, int n_in,
                              void* d_out, int out_size)
{
    const float* x    = (const float*)d_in[0];
    const int*   mask = (const int*)  d_in[1];
    const float* wq   = (const float*)d_in[2];
    const float* wk   = (const float*)d_in[3];
    const float* wv   = (const float*)d_in[4];
    const float* wo   = (const float*)d_in[5];
    const float* f1w  = (const float*)d_in[6];
    const float* f1b  = (const float*)d_in[7];
    const float* f2w  = (const float*)d_in[8];
    const float* f2b  = (const float*)d_in[9];
    const float* l1a  = (const float*)d_in[10];
    const float* l1b  = (const float*)d_in[11];
    const float* l2a  = (const float*)d_in[12];
    const float* l2b  = (const float*)d_in[13];
    float* out = (float*)d_out;

    float *xn, *q, *k, *v, *at, *h, *hn, *ac;
    cudaGetSymbolAddress((void**)&xn, g_xn);
    cudaGetSymbolAddress((void**)&q,  g_q);
    cudaGetSymbolAddress((void**)&k,  g_k);
    cudaGetSymbolAddress((void**)&v,  g_v);
    cudaGetSymbolAddress((void**)&at, g_at);
    cudaGetSymbolAddress((void**)&h,  g_h);
    cudaGetSymbolAddress((void**)&hn, g_hn);
    cudaGetSymbolAddress((void**)&ac, g_ac);

    cudaFuncSetAttribute(tc_gemm<0,0,0>, cudaFuncAttributeMaxDynamicSharedMemorySize, GSMEM);
    cudaFuncSetAttribute(tc_gemm<0,0,1>, cudaFuncAttributeMaxDynamicSharedMemorySize, GSMEM);
    cudaFuncSetAttribute(tc_gemm<1,1,0>, cudaFuncAttributeMaxDynamicSharedMemorySize, GSMEM);
    cudaFuncSetAttribute(tc_gemm<1,0,1>, cudaFuncAttributeMaxDynamicSharedMemorySize, GSMEM);
    cudaFuncSetAttribute(attn_tc, cudaFuncAttributeMaxDynamicSharedMemorySize, ASMEM);

    // 1. ln1
    ln_kernel<<<MTOT, 256>>>(x, l1a, l1b, xn);
    // 2. QKV projections
    dim3 gEE(EMB / 128, MTOT / 128);
    tc_gemm<0,0,0><<<gEE, 512, GSMEM>>>(xn, wq, nullptr, nullptr, q, MTOT, EMB, EMB);
    tc_gemm<0,0,0><<<gEE, 512, GSMEM>>>(xn, wk, nullptr, nullptr, k, MTOT, EMB, EMB);
    tc_gemm<0,0,0><<<gEE, 512, GSMEM>>>(xn, wv, nullptr, nullptr, v, MTOT, EMB, EMB);
    // 3. attention
    attn_tc<<<dim3(SQ / 64, NH, BATCH), 256, ASMEM>>>(q, k, v, mask, at);
    // 4. output projection + residual
    tc_gemm<0,0,1><<<gEE, 512, GSMEM>>>(at, wo, nullptr, x, h, MTOT, EMB, EMB);
    // 5. ln2
    ln_kernel<<<MTOT, 256>>>(h, l2a, l2b, hn);
    // 6. FFN
    tc_gemm<1,1,0><<<dim3(HID / 128, MTOT / 128), 512, GSMEM>>>(hn, f1w, f1b, nullptr, ac, MTOT, HID, EMB);
    tc_gemm<1,0,1><<<gEE, 512, GSMEM>>>(ac, f2w, f2b, h, out, MTOT, EMB, HID);
}

// round 9
// speedup vs baseline: 2.6371x; 1.2787x over previous
#include <cuda_runtime.h>
#include <cuda_bf16.h>
#include <cstdint>
#include <math.h>

#define EMB   1024
#define HID   4096
#define NH    16
#define DKH   64
#define SQ    2048
#define BATCH 2
#define MTOT  (BATCH*SQ)   // 4096 rows

typedef __nv_bfloat16 bf16;

// ---------------- scratch (device globals: allocation-free) ----------------
__device__ float g_q [(size_t)MTOT*EMB];
__device__ float g_k [(size_t)MTOT*EMB];
__device__ float g_v [(size_t)MTOT*EMB];
__device__ float g_h [(size_t)MTOT*EMB];
__device__ bf16  g_xnh[(size_t)MTOT*EMB],  g_xnl[(size_t)MTOT*EMB];
__device__ bf16  g_ath[(size_t)MTOT*EMB],  g_atl[(size_t)MTOT*EMB];
__device__ bf16  g_hnh[(size_t)MTOT*EMB],  g_hnl[(size_t)MTOT*EMB];
__device__ bf16  g_ach[(size_t)MTOT*HID],  g_acl[(size_t)MTOT*HID];
__device__ bf16  g_wqh[(size_t)EMB*EMB],   g_wql[(size_t)EMB*EMB];
__device__ bf16  g_wkh[(size_t)EMB*EMB],   g_wkl[(size_t)EMB*EMB];
__device__ bf16  g_wvh[(size_t)EMB*EMB],   g_wvl[(size_t)EMB*EMB];
__device__ bf16  g_woh[(size_t)EMB*EMB],   g_wol[(size_t)EMB*EMB];
__device__ bf16  g_f1h[(size_t)EMB*HID],   g_f1l[(size_t)EMB*HID];
__device__ bf16  g_f2h[(size_t)EMB*HID],   g_f2l[(size_t)EMB*HID];

// ======================= helpers ===========================================
__device__ __forceinline__ uint32_t s2u(const void* p) {
    uint32_t a;
    asm("{ .reg .u64 t; cvta.to.shared.u64 t, %1; cvt.u32.u64 %0, t; }"
        : "=r"(a) : "l"(p));
    return a;
}
__device__ __forceinline__ void ldsm4(uint32_t* r, uint32_t addr) {
    asm volatile("ldmatrix.sync.aligned.m8n8.x4.shared.b16 {%0,%1,%2,%3}, [%4];"
                 : "=r"(r[0]), "=r"(r[1]), "=r"(r[2]), "=r"(r[3]) : "r"(addr));
}
__device__ __forceinline__ void ldsm4t(uint32_t* r, uint32_t addr) {
    asm volatile("ldmatrix.sync.aligned.m8n8.x4.trans.shared.b16 {%0,%1,%2,%3}, [%4];"
                 : "=r"(r[0]), "=r"(r[1]), "=r"(r[2]), "=r"(r[3]) : "r"(addr));
}
__device__ __forceinline__ void mma16816(float* d, const uint32_t* a,
                                         const uint32_t b0, const uint32_t b1) {
    asm volatile(
        "mma.sync.aligned.m16n8k16.row.col.f32.bf16.bf16.f32 "
        "{%0,%1,%2,%3}, {%4,%5,%6,%7}, {%8,%9}, {%0,%1,%2,%3};"
        : "+f"(d[0]), "+f"(d[1]), "+f"(d[2]), "+f"(d[3])
        : "r"(a[0]), "r"(a[1]), "r"(a[2]), "r"(a[3]), "r"(b0), "r"(b1));
}
__device__ __forceinline__ uint32_t packbf(float a, float b) {
    bf16 ha = __float2bfloat16(a), hb = __float2bfloat16(b);
    return (uint32_t)__bfloat16_as_ushort(ha)
         | ((uint32_t)__bfloat16_as_ushort(hb) << 16);
}
__device__ __forceinline__ float bferr(float v) {
    return v - __bfloat162float(__float2bfloat16(v));
}
__device__ __forceinline__ void cpa16(uint32_t dst, const void* src) {
    asm volatile("cp.async.cg.shared.global [%0], [%1], 16;"
                 :: "r"(dst), "l"(src));
}
#define CP_COMMIT() asm volatile("cp.async.commit_group;" ::: "memory")
#define CP_WAIT1()  asm volatile("cp.async.wait_group 1;" ::: "memory")

// ---------------- fp32 -> bf16 hi/lo split (weights pre-pass) --------------
__global__ void split_k(const float* __restrict__ s,
                        bf16* __restrict__ hi, bf16* __restrict__ lo, int n2)
{
    const int i = blockIdx.x * blockDim.x + threadIdx.x;
    if (i >= n2) return;
    float2 v = ((const float2*)s)[i];
    ((uint32_t*)hi)[i] = packbf(v.x, v.y);
    ((uint32_t*)lo)[i] = packbf(bferr(v.x), bferr(v.y));
}

// ======================= split-bf16 cp.async GEMM ==========================
// C[M,N] = (Ahi+Alo)[M,K] @ (Bhi+Blo)[K,N] (+bias)(+relu)(+res)
// 128x128 CTA, BK=32, 256 thr (8 warps, 2x4), warp tile 64x32, 3-stage pipe.
#define ASTRIDE 40
#define BSTRIDE 136
#define AH_B    0
#define AL_B    10240
#define BH_B    20480
#define BL_B    29184
#define STAGE_B 37888
#define GSMEM   (3*STAGE_B)

template<int BIAS, int RELU, int RES, int SPLIT>
__global__ void __launch_bounds__(256, 2) tc_gemm(
    const bf16* __restrict__ Ahi, const bf16* __restrict__ Alo,
    const bf16* __restrict__ Bhi, const bf16* __restrict__ Blo,
    const float* __restrict__ bias, const float* __restrict__ res,
    float* __restrict__ C, bf16* __restrict__ Chi, bf16* __restrict__ Clo,
    int M, int N, int K)
{
    extern __shared__ char sm[];
    const uint32_t sbase = s2u(sm);
    const int tid = threadIdx.x, lane = tid & 31, wid = tid >> 5;
    const int wm = wid >> 2, wn = wid & 3;           // 2 x 4 warp grid
    const int bm = blockIdx.y * 128, bn = blockIdx.x * 128;

    float acc[4][4][4];
    #pragma unroll
    for (int i = 0; i < 4; i++)
        #pragma unroll
        for (int j = 0; j < 4; j++)
            #pragma unroll
            for (int e = 0; e < 4; e++) acc[i][j][e] = 0.f;

    const int a_r = wm * 64 + (lane & 15);
    const int a_c = (lane >> 4) * 8;
    const int b_r = lane & 15;
    const int b_c = wn * 32 + (lane >> 4) * 8;
    const int nch = K >> 5;

    // cp.async mapping (per thread: 2 segs per array)
    const int ar0 = tid >> 2, as0 = (tid & 3) * 8;           // A: row, col-seg
    const int br0 = tid >> 4, bs0 = (tid & 15) * 8;          // B: row, col-seg

    auto CP = [&](int c) {
        const int k0 = c << 5;
        const uint32_t base = sbase + (c % 3) * STAGE_B;
        #pragma unroll
        for (int i = 0; i < 2; i++) {
            const int row = ar0 + i * 64;
            const uint32_t d = base + (uint32_t)(row * ASTRIDE + as0) * 2;
            cpa16(d + AH_B, Ahi + (size_t)(bm + row) * K + k0 + as0);
            cpa16(d + AL_B, Alo + (size_t)(bm + row) * K + k0 + as0);
        }
        #pragma unroll
        for (int i = 0; i < 2; i++) {
            const int row = br0 + i * 16;
            const uint32_t d = base + (uint32_t)(row * BSTRIDE + bs0) * 2;
            cpa16(d + BH_B, Bhi + (size_t)(k0 + row) * N + bn + bs0);
            cpa16(d + BL_B, Blo + (size_t)(k0 + row) * N + bn + bs0);
        }
        CP_COMMIT();
    };
    auto MMAS = [&](int slot) {
        const uint32_t stg = sbase + slot * STAGE_B;
        #pragma unroll
        for (int ks = 0; ks < 2; ks++) {
            uint32_t ah[4][4], al[4][4], bh[2][4], bl[2][4];
            #pragma unroll
            for (int mi = 0; mi < 4; mi++) {
                const uint32_t off =
                    ((a_r + mi * 16) * ASTRIDE + ks * 16 + a_c) * 2;
                ldsm4(ah[mi], stg + AH_B + off);
                ldsm4(al[mi], stg + AL_B + off);
            }
            #pragma unroll
            for (int np = 0; np < 2; np++) {
                const uint32_t off =
                    ((b_r + ks * 16) * BSTRIDE + b_c + np * 16) * 2;
                ldsm4t(bh[np], stg + BH_B + off);
                ldsm4t(bl[np], stg + BL_B + off);
            }
            #pragma unroll
            for (int mi = 0; mi < 4; mi++)
                #pragma unroll
                for (int ni = 0; ni < 4; ni++) {
                    const int np = ni >> 1, pr = (ni & 1) * 2;
                    mma16816(acc[mi][ni], ah[mi], bh[np][pr], bh[np][pr + 1]);
                    mma16816(acc[mi][ni], ah[mi], bl[np][pr], bl[np][pr + 1]);
                    mma16816(acc[mi][ni], al[mi], bh[np][pr], bh[np][pr + 1]);
                }
        }
    };

    CP(0);
    CP(1);
    for (int c = 0; c < nch; c++) {
        CP_WAIT1();
        __syncthreads();
        if (c + 2 < nch) CP(c + 2);
        MMAS(c % 3);
    }

    // ---- epilogue ----
    const int g = lane >> 2, t4 = lane & 3;
    #pragma unroll
    for (int mi = 0; mi < 4; mi++) {
        const int r0 = bm + wm * 64 + mi * 16 + g;
        #pragma unroll
        for (int half = 0; half < 2; half++) {
            const int row = r0 + half * 8;
            #pragma unroll
            for (int ni = 0; ni < 4; ni++) {
                const int col = bn + wn * 32 + ni * 8 + t4 * 2;
                float v0 = acc[mi][ni][half * 2 + 0];
                float v1 = acc[mi][ni][half * 2 + 1];
                if (BIAS) { v0 += bias[col]; v1 += bias[col + 1]; }
                if (RELU) { v0 = fmaxf(v0, 0.f); v1 = fmaxf(v1, 0.f); }
                if (RES) {
                    const float2 rv = *(const float2*)(res + (size_t)row * N + col);
                    v0 += rv.x; v1 += rv.y;
                }
                if (SPLIT) {
                    ((uint32_t*)(Chi + (size_t)row * N + col))[0] = packbf(v0, v1);
                    ((uint32_t*)(Clo + (size_t)row * N + col))[0] =
                        packbf(bferr(v0), bferr(v1));
                } else {
                    *(float2*)(C + (size_t)row * N + col) = make_float2(v0, v1);
                }
            }
        }
    }
}

// ---------------- LayerNorm (Bessel var, /(std+eps)) -> bf16 hi/lo ---------
__global__ void ln_kernel(const float* __restrict__ in,
                          const float* __restrict__ alpha,
                          const float* __restrict__ beta,
                          bf16* __restrict__ ohi, bf16* __restrict__ olo)
{
    __shared__ float row[EMB];
    __shared__ float red[8];
    const int r   = blockIdx.x;
    const int tid = threadIdx.x;
    const float* p = in + (size_t)r * EMB;

    float s = 0.f;
    #pragma unroll
    for (int i = tid; i < EMB; i += 256) { float v = p[i]; row[i] = v; s += v; }
    #pragma unroll
    for (int o = 16; o; o >>= 1) s += __shfl_xor_sync(0xffffffffu, s, o);
    if ((tid & 31) == 0) red[tid >> 5] = s;
    __syncthreads();
    if (tid < 8) {
        float t = red[tid];
        #pragma unroll
        for (int o = 4; o; o >>= 1) t += __shfl_xor_sync(0xffu, t, o);
        if (tid == 0) red[0] = t;
    }
    __syncthreads();
    const float mean = red[0] * (1.f / EMB);

    float s2 = 0.f;
    #pragma unroll
    for (int i = tid; i < EMB; i += 256) { float d = row[i] - mean; s2 += d * d; }
    #pragma unroll
    for (int o = 16; o; o >>= 1) s2 += __shfl_xor_sync(0xffffffffu, s2, o);
    __syncthreads();
    if ((tid & 31) == 0) red[tid >> 5] = s2;
    __syncthreads();
    if (tid < 8) {
        float t = red[tid];
        #pragma unroll
        for (int o = 4; o; o >>= 1) t += __shfl_xor_sync(0xffu, t, o);
        if (tid == 0) red[0] = t;
    }
    __syncthreads();
    const float var   = red[0] * (1.f / (EMB - 1));
    const float scale = alpha[0] / (sqrtf(var) + 1e-6f);
    const float bias  = beta[0];

    #pragma unroll
    for (int i = tid; i < EMB; i += 256) {
        const float v = (row[i] - mean) * scale + bias;
        ohi[(size_t)r * EMB + i] = __float2bfloat16(v);
        olo[(size_t)r * EMB + i] = __float2bfloat16(bferr(v));
    }
}

// =============== tensor-core flash attention (split bf16) ==================
#define TSTR   72
#define KTHI_O 0
#define KTLO_O 9216
#define VHI_O  18432
#define VLO_O  27648
#define PHI_O  36864
#define PLO_O  46080
#define REDM_O 55296
#define REDL_O 55808
#define ASMEM  56320

__global__ void __launch_bounds__(256, 2) attn_tc(
    const float* __restrict__ Q, const float* __restrict__ Kg,
    const float* __restrict__ Vg, const int* __restrict__ mask,
    bf16* __restrict__ Ohi, bf16* __restrict__ Olo)
{
    extern __shared__ char asm_[];
    const uint32_t sb = s2u(asm_);
    bf16* smb = (bf16*)asm_;
    float* redm = (float*)(asm_ + REDM_O);
    float* redl = (float*)(asm_ + REDL_O);

    const int b  = blockIdx.z, h = blockIdx.y;
    const int q0 = blockIdx.x * 64;
    const int tid = threadIdx.x, lane = tid & 31, wid = tid >> 5;
    const int wm = wid >> 1, wn = wid & 1;
    const int g = lane >> 2, t4 = lane & 3;
    const size_t base = (size_t)b * SQ * EMB + (size_t)h * DKH;

    {
        const int qr = tid >> 2, c0 = (tid & 3) * 16;
        const float4* Qp = (const float4*)(Q + base + (size_t)(q0 + qr) * EMB + c0);
        #pragma unroll
        for (int i = 0; i < 4; i++) {
            float4 v = Qp[i];
            v.x *= 0.125f; v.y *= 0.125f; v.z *= 0.125f; v.w *= 0.125f;
            uint2 hi = make_uint2(packbf(v.x, v.y), packbf(v.z, v.w));
            uint2 lo = make_uint2(packbf(bferr(v.x), bferr(v.y)),
                                  packbf(bferr(v.z), bferr(v.w)));
            const int off = qr * TSTR + c0 + i * 4;
            *(uint2*)(smb + PHI_O / 2 + off) = hi;
            *(uint2*)(smb + PLO_O / 2 + off) = lo;
        }
    }
    __syncthreads();

    uint32_t qh[4][4], ql[4][4];
    {
        const int a_r = wm * 16 + (lane & 15);
        const int a_c = (lane >> 4) * 8;
        #pragma unroll
        for (int ks = 0; ks < 4; ks++) {
            const uint32_t off = (a_r * TSTR + ks * 16 + a_c) * 2;
            ldsm4(qh[ks], sb + PHI_O + off);
            ldsm4(ql[ks], sb + PLO_O + off);
        }
    }

    float m_r[2] = {-1e30f, -1e30f}, l_r[2] = {0.f, 0.f};
    float acc_o[4][4];
    #pragma unroll
    for (int ni = 0; ni < 4; ni++)
        #pragma unroll
        for (int e = 0; e < 4; e++) acc_o[ni][e] = 0.f;

    for (int j0 = 0; j0 < SQ; j0 += 64) {
        __syncthreads();
        {
            const int jj = (tid & 31) * 2, d0 = (tid >> 5) * 4;
            #pragma unroll
            for (int r = 0; r < 2; r++) {
                const int d = d0 + r * 32;
                float4 a = *(const float4*)(Kg + base + (size_t)(j0 + jj) * EMB + d);
                float4 c = *(const float4*)(Kg + base + (size_t)(j0 + jj + 1) * EMB + d);
                const float av[4] = {a.x, a.y, a.z, a.w};
                const float cv[4] = {c.x, c.y, c.z, c.w};
                #pragma unroll
                for (int i = 0; i < 4; i++) {
                    const int off = (d + i) * TSTR + jj;
                    *(uint32_t*)(smb + KTHI_O / 2 + off) = packbf(av[i], cv[i]);
                    *(uint32_t*)(smb + KTLO_O / 2 + off) =
                        packbf(bferr(av[i]), bferr(cv[i]));
                }
            }
        }
        {
            const int vr = tid >> 2, c0 = (tid & 3) * 16;
            const float4* Vp = (const float4*)(Vg + base + (size_t)(j0 + vr) * EMB + c0);
            #pragma unroll
            for (int i = 0; i < 4; i++) {
                float4 v = Vp[i];
                uint2 hi = make_uint2(packbf(v.x, v.y), packbf(v.z, v.w));
                uint2 lo = make_uint2(packbf(bferr(v.x), bferr(v.y)),
                                      packbf(bferr(v.z), bferr(v.w)));
                const int off = vr * TSTR + c0 + i * 4;
                *(uint2*)(smb + VHI_O / 2 + off) = hi;
                *(uint2*)(smb + VLO_O / 2 + off) = lo;
            }
        }
        __syncthreads();

        float s[4][4];
        #pragma unroll
        for (int ni = 0; ni < 4; ni++)
            #pragma unroll
            for (int e = 0; e < 4; e++) s[ni][e] = 0.f;
        #pragma unroll
        for (int ks = 0; ks < 4; ks++) {
            uint32_t bh[2][4], bl[2][4];
            #pragma unroll
            for (int np = 0; np < 2; np++) {
                const uint32_t off =
                    (((lane & 15) + ks * 16) * TSTR
                     + wn * 32 + np * 16 + (lane >> 4) * 8) * 2;
                ldsm4t(bh[np], sb + KTHI_O + off);
                ldsm4t(bl[np], sb + KTLO_O + off);
            }
            #pragma unroll
            for (int ni = 0; ni < 4; ni++) {
                const int np = ni >> 1, pr = (ni & 1) * 2;
                mma16816(s[ni], qh[ks], bh[np][pr], bh[np][pr + 1]);
                mma16816(s[ni], qh[ks], bl[np][pr], bl[np][pr + 1]);
                mma16816(s[ni], ql[ks], bh[np][pr], bh[np][pr + 1]);
            }
        }

        #pragma unroll
        for (int ni = 0; ni < 4; ni++) {
            const int c = j0 + wn * 32 + ni * 8 + t4 * 2;
            int2 mk = *(const int2*)(mask + b * SQ + c);
            if (mk.x == 0) { s[ni][0] = -1e30f; s[ni][2] = -1e30f; }
            if (mk.y == 0) { s[ni][1] = -1e30f; s[ni][3] = -1e30f; }
        }

        float lmax[2] = {-1e30f, -1e30f};
        #pragma unroll
        for (int ni = 0; ni < 4; ni++) {
            lmax[0] = fmaxf(lmax[0], fmaxf(s[ni][0], s[ni][1]));
            lmax[1] = fmaxf(lmax[1], fmaxf(s[ni][2], s[ni][3]));
        }
        #pragma unroll
        for (int o = 1; o <= 2; o <<= 1) {
            lmax[0] = fmaxf(lmax[0], __shfl_xor_sync(0xffffffffu, lmax[0], o));
            lmax[1] = fmaxf(lmax[1], __shfl_xor_sync(0xffffffffu, lmax[1], o));
        }
        if (t4 == 0) {
            redm[wn * 64 + wm * 16 + g] = lmax[0];
            redm[wn * 64 + wm * 16 + g + 8] = lmax[1];
        }
        __syncthreads();
        float mn[2], corr[2];
        #pragma unroll
        for (int r = 0; r < 2; r++) {
            const int row = wm * 16 + g + r * 8;
            const float tm = fmaxf(redm[row], redm[64 + row]);
            mn[r] = fmaxf(m_r[r], tm);
            corr[r] = __expf(m_r[r] - mn[r]);
            m_r[r] = mn[r];
        }
        float lsum[2] = {0.f, 0.f};
        #pragma unroll
        for (int ni = 0; ni < 4; ni++) {
            float p0 = __expf(s[ni][0] - mn[0]);
            float p1 = __expf(s[ni][1] - mn[0]);
            float p2 = __expf(s[ni][2] - mn[1]);
            float p3 = __expf(s[ni][3] - mn[1]);
            lsum[0] += p0 + p1; lsum[1] += p2 + p3;
            const int colb = wn * 32 + ni * 8 + t4 * 2;
            const int off0 = (wm * 16 + g) * TSTR + colb;
            const int off8 = (wm * 16 + g + 8) * TSTR + colb;
            *(uint32_t*)(smb + PHI_O / 2 + off0) = packbf(p0, p1);
            *(uint32_t*)(smb + PLO_O / 2 + off0) = packbf(bferr(p0), bferr(p1));
            *(uint32_t*)(smb + PHI_O / 2 + off8) = packbf(p2, p3);
            *(uint32_t*)(smb + PLO_O / 2 + off8) = packbf(bferr(p2), bferr(p3));
        }
        #pragma unroll
        for (int o = 1; o <= 2; o <<= 1) {
            lsum[0] += __shfl_xor_sync(0xffffffffu, lsum[0], o);
            lsum[1] += __shfl_xor_sync(0xffffffffu, lsum[1], o);
        }
        if (t4 == 0) {
            redl[wn * 64 + wm * 16 + g] = lsum[0];
            redl[wn * 64 + wm * 16 + g + 8] = lsum[1];
        }
        __syncthreads();
        #pragma unroll
        for (int r = 0; r < 2; r++) {
            const int row = wm * 16 + g + r * 8;
            l_r[r] = l_r[r] * corr[r] + redl[row] + redl[64 + row];
        }
        #pragma unroll
        for (int ni = 0; ni < 4; ni++) {
            acc_o[ni][0] *= corr[0]; acc_o[ni][1] *= corr[0];
            acc_o[ni][2] *= corr[1]; acc_o[ni][3] *= corr[1];
        }

        #pragma unroll
        for (int ks = 0; ks < 4; ks++) {
            uint32_t ph[4], pl[4], vh[2][4], vl[2][4];
            {
                const uint32_t off =
                    ((wm * 16 + (lane & 15)) * TSTR + ks * 16 + (lane >> 4) * 8) * 2;
                ldsm4(ph, sb + PHI_O + off);
                ldsm4(pl, sb + PLO_O + off);
            }
            #pragma unroll
            for (int np = 0; np < 2; np++) {
                const uint32_t off =
                    (((lane & 15) + ks * 16) * TSTR
                     + wn * 32 + np * 16 + (lane >> 4) * 8) * 2;
                ldsm4t(vh[np], sb + VHI_O + off);
                ldsm4t(vl[np], sb + VLO_O + off);
            }
            #pragma unroll
            for (int ni = 0; ni < 4; ni++) {
                const int np = ni >> 1, pr = (ni & 1) * 2;
                mma16816(acc_o[ni], ph, vh[np][pr], vh[np][pr + 1]);
                mma16816(acc_o[ni], ph, vl[np][pr], vl[np][pr + 1]);
                mma16816(acc_o[ni], pl, vh[np][pr], vh[np][pr + 1]);
            }
        }
    }

    // ---- write O as bf16 hi/lo ----
    const float inv0 = 1.f / l_r[0], inv1 = 1.f / l_r[1];
    #pragma unroll
    for (int r = 0; r < 2; r++) {
        const int qrow = q0 + wm * 16 + g + r * 8;
        const size_t ob = (size_t)(b * SQ + qrow) * EMB + h * DKH;
        const float inv = r ? inv1 : inv0;
        #pragma unroll
        for (int ni = 0; ni < 4; ni++) {
            const int col = wn * 32 + ni * 8 + t4 * 2;
            const float v0 = acc_o[ni][r * 2 + 0] * inv;
            const float v1 = acc_o[ni][r * 2 + 1] * inv;
            *(uint32_t*)(Ohi + ob + col) = packbf(v0, v1);
            *(uint32_t*)(Olo + ob + col) = packbf(bferr(v0), bferr(v1));
        }
    }
}

// ---------------------------- launcher -------------------------------------
extern "C" void kernel_launch(void* const* d_in, const int* in_sizes, int n_in,
                              void* d_out, int out_size)
{
    const float* x    = (const float*)d_in[0];
    const int*   mask = (const int*)  d_in[1];
    const float* wq   = (const float*)d_in[2];
    const float* wk   = (const float*)d_in[3];
    const float* wv   = (const float*)d_in[4];
    const float* wo   = (const float*)d_in[5];
    const float* f1w  = (const float*)d_in[6];
    const float* f1b  = (const float*)d_in[7];
    const float* f2w  = (const float*)d_in[8];
    const float* f2b  = (const float*)d_in[9];
    const float* l1a  = (const float*)d_in[10];
    const float* l1b  = (const float*)d_in[11];
    const float* l2a  = (const float*)d_in[12];
    const float* l2b  = (const float*)d_in[13];
    float* out = (float*)d_out;

    float *q, *k, *v, *h;
    bf16 *xnh, *xnl, *ath, *atl, *hnh, *hnl, *ach, *acl;
    bf16 *wqh, *wql, *wkh, *wkl, *wvh, *wvl, *woh, *wol, *f1h, *f1l, *f2h, *f2l;
    cudaGetSymbolAddress((void**)&q,   g_q);
    cudaGetSymbolAddress((void**)&k,   g_k);
    cudaGetSymbolAddress((void**)&v,   g_v);
    cudaGetSymbolAddress((void**)&h,   g_h);
    cudaGetSymbolAddress((void**)&xnh, g_xnh); cudaGetSymbolAddress((void**)&xnl, g_xnl);
    cudaGetSymbolAddress((void**)&ath, g_ath); cudaGetSymbolAddress((void**)&atl, g_atl);
    cudaGetSymbolAddress((void**)&hnh, g_hnh); cudaGetSymbolAddress((void**)&hnl, g_hnl);
    cudaGetSymbolAddress((void**)&ach, g_ach); cudaGetSymbolAddress((void**)&acl, g_acl);
    cudaGetSymbolAddress((void**)&wqh, g_wqh); cudaGetSymbolAddress((void**)&wql, g_wql);
    cudaGetSymbolAddress((void**)&wkh, g_wkh); cudaGetSymbolAddress((void**)&wkl, g_wkl);
    cudaGetSymbolAddress((void**)&wvh, g_wvh); cudaGetSymbolAddress((void**)&wvl, g_wvl);
    cudaGetSymbolAddress((void**)&woh, g_woh); cudaGetSymbolAddress((void**)&wol, g_wol);
    cudaGetSymbolAddress((void**)&f1h, g_f1h); cudaGetSymbolAddress((void**)&f1l, g_f1l);
    cudaGetSymbolAddress((void**)&f2h, g_f2h); cudaGetSymbolAddress((void**)&f2l, g_f2l);

    cudaFuncSetAttribute(tc_gemm<0,0,0,0>, cudaFuncAttributeMaxDynamicSharedMemorySize, GSMEM);
    cudaFuncSetAttribute(tc_gemm<0,0,1,0>, cudaFuncAttributeMaxDynamicSharedMemorySize, GSMEM);
    cudaFuncSetAttribute(tc_gemm<1,1,0,1>, cudaFuncAttributeMaxDynamicSharedMemorySize, GSMEM);
    cudaFuncSetAttribute(tc_gemm<1,0,1,0>, cudaFuncAttributeMaxDynamicSharedMemorySize, GSMEM);
    cudaFuncSetAttribute(attn_tc, cudaFuncAttributeMaxDynamicSharedMemorySize, ASMEM);

    // 0. split weights to bf16 hi/lo
    const int n2e = EMB * EMB / 2, n2f = EMB * HID / 2;
    split_k<<<n2e / 256, 256>>>(wq,  wqh, wql, n2e);
    split_k<<<n2e / 256, 256>>>(wk,  wkh, wkl, n2e);
    split_k<<<n2e / 256, 256>>>(wv,  wvh, wvl, n2e);
    split_k<<<n2e / 256, 256>>>(wo,  woh, wol, n2e);
    split_k<<<n2f / 256, 256>>>(f1w, f1h, f1l, n2f);
    split_k<<<n2f / 256, 256>>>(f2w, f2h, f2l, n2f);

    // 1. ln1 -> xn hi/lo
    ln_kernel<<<MTOT, 256>>>(x, l1a, l1b, xnh, xnl);
    // 2. QKV projections (fp32 out)
    dim3 gEE(EMB / 128, MTOT / 128);
    tc_gemm<0,0,0,0><<<gEE, 256, GSMEM>>>(xnh, xnl, wqh, wql, nullptr, nullptr,
                                          q, nullptr, nullptr, MTOT, EMB, EMB);
    tc_gemm<0,0,0,0><<<gEE, 256, GSMEM>>>(xnh, xnl, wkh, wkl, nullptr, nullptr,
                                          k, nullptr, nullptr, MTOT, EMB, EMB);
    tc_gemm<0,0,0,0><<<gEE, 256, GSMEM>>>(xnh, xnl, wvh, wvl, nullptr, nullptr,
                                          v, nullptr, nullptr, MTOT, EMB, EMB);
    // 3. attention -> at hi/lo
    attn_tc<<<dim3(SQ / 64, NH, BATCH), 256, ASMEM>>>(q, k, v, mask, ath, atl);
    // 4. output projection + residual -> h fp32
    tc_gemm<0,0,1,0><<<gEE, 256, GSMEM>>>(ath, atl, woh, wol, nullptr, x,
                                          h, nullptr, nullptr, MTOT, EMB, EMB);
    // 5. ln2 -> hn hi/lo
    ln_kernel<<<MTOT, 256>>>(h, l2a, l2b, hnh, hnl);
    // 6. FFN: ff1 -> ac hi/lo (split only), ff2 -> out fp32
    tc_gemm<1,1,0,1><<<dim3(HID / 128, MTOT / 128), 256, GSMEM>>>(
        hnh, hnl, f1h, f1l, f1b, nullptr, nullptr, ach, acl, MTOT, HID, EMB);
    tc_gemm<1,0,1,0><<<gEE, 256, GSMEM>>>(ach, acl, f2h, f2l, f2b, h,
                                          out, nullptr, nullptr, MTOT, EMB, HID);
}

// round 13
// speedup vs baseline: 3.9676x; 1.5046x over previous
#include <cuda_runtime.h>
#include <cuda_bf16.h>
#include <cstdint>
#include <math.h>

#define EMB   1024
#define HID   4096
#define NH    16
#define DKH   64
#define SQ    2048
#define BATCH 2
#define MTOT  (BATCH*SQ)   // 4096 rows

typedef __nv_bfloat16 bf16;

// ---------------- scratch (device globals: allocation-free) ----------------
__device__ float g_h [(size_t)MTOT*EMB];
__device__ bf16  g_qh [(size_t)MTOT*EMB];
__device__ bf16  g_kh [(size_t)MTOT*EMB];
__device__ bf16  g_vh [(size_t)MTOT*EMB];
__device__ bf16  g_xnh[(size_t)MTOT*EMB];
__device__ bf16  g_ath[(size_t)MTOT*EMB];
__device__ bf16  g_hnh[(size_t)MTOT*EMB],  g_hnl[(size_t)MTOT*EMB];
__device__ bf16  g_ach[(size_t)MTOT*HID],  g_acl[(size_t)MTOT*HID];
__device__ bf16  g_wqh[(size_t)EMB*EMB];
__device__ bf16  g_wkh[(size_t)EMB*EMB];
__device__ bf16  g_wvh[(size_t)EMB*EMB];
__device__ bf16  g_woh[(size_t)EMB*EMB];
__device__ bf16  g_f1h[(size_t)EMB*HID],   g_f1l[(size_t)EMB*HID];
__device__ bf16  g_f2h[(size_t)EMB*HID],   g_f2l[(size_t)EMB*HID];

// ======================= helpers ===========================================
__device__ __forceinline__ uint32_t s2u(const void* p) {
    uint32_t a;
    asm("{ .reg .u64 t; cvta.to.shared.u64 t, %1; cvt.u32.u64 %0, t; }"
        : "=r"(a) : "l"(p));
    return a;
}
__device__ __forceinline__ void ldsm4(uint32_t* r, uint32_t addr) {
    asm volatile("ldmatrix.sync.aligned.m8n8.x4.shared.b16 {%0,%1,%2,%3}, [%4];"
                 : "=r"(r[0]), "=r"(r[1]), "=r"(r[2]), "=r"(r[3]) : "r"(addr));
}
__device__ __forceinline__ void ldsm4t(uint32_t* r, uint32_t addr) {
    asm volatile("ldmatrix.sync.aligned.m8n8.x4.trans.shared.b16 {%0,%1,%2,%3}, [%4];"
                 : "=r"(r[0]), "=r"(r[1]), "=r"(r[2]), "=r"(r[3]) : "r"(addr));
}
__device__ __forceinline__ void mma16816(float* d, const uint32_t* a,
                                         const uint32_t b0, const uint32_t b1) {
    asm volatile(
        "mma.sync.aligned.m16n8k16.row.col.f32.bf16.bf16.f32 "
        "{%0,%1,%2,%3}, {%4,%5,%6,%7}, {%8,%9}, {%0,%1,%2,%3};"
        : "+f"(d[0]), "+f"(d[1]), "+f"(d[2]), "+f"(d[3])
        : "r"(a[0]), "r"(a[1]), "r"(a[2]), "r"(a[3]), "r"(b0), "r"(b1));
}
__device__ __forceinline__ uint32_t packbf(float a, float b) {
    bf16 ha = __float2bfloat16(a), hb = __float2bfloat16(b);
    return (uint32_t)__bfloat16_as_ushort(ha)
         | ((uint32_t)__bfloat16_as_ushort(hb) << 16);
}
__device__ __forceinline__ float bferr(float v) {
    return v - __bfloat162float(__float2bfloat16(v));
}
__device__ __forceinline__ void cpa16(uint32_t dst, const void* src) {
    asm volatile("cp.async.cg.shared.global [%0], [%1], 16;"
                 :: "r"(dst), "l"(src));
}
#define CP_COMMIT() asm volatile("cp.async.commit_group;" ::: "memory")
#define CP_WAIT1()  asm volatile("cp.async.wait_group 1;" ::: "memory")
#define CP_WAIT0()  asm volatile("cp.async.wait_group 0;" ::: "memory")
__device__ __forceinline__ uint32_t swz(uint32_t o) {
    return o ^ ((o >> 3) & 0x70);
}

// ---------------- fp32 -> bf16 split pre-pass ------------------------------
template<int LO>
__global__ void split_k(const float* __restrict__ s,
                        bf16* __restrict__ hi, bf16* __restrict__ lo, int n2)
{
    const int i = blockIdx.x * blockDim.x + threadIdx.x;
    if (i >= n2) return;
    float2 v = ((const float2*)s)[i];
    ((uint32_t*)hi)[i] = packbf(v.x, v.y);
    if (LO) ((uint32_t*)lo)[i] = packbf(bferr(v.x), bferr(v.y));
}

// ======================= 1-pass bf16 cp.async GEMM =========================
// C[M,N] = Ahi[M,K] @ Bhi[K,N]; out bf16 (OUTBF) or fp32 (+RES residual).
// 128x128 CTA, BK=32, 256 thr (8 warps, 2x4), warp tile 64x32, 3-stage pipe.
#define A1STR  40
#define B1STR  136
#define A1_B   0
#define B1_B   10240
#define ST1_B  18944
#define G1SMEM (3*ST1_B)

template<int RES, int OUTBF>
__global__ void __launch_bounds__(256, 2) tc_gemm1(
    const bf16* __restrict__ Ahi, const bf16* __restrict__ Bhi,
    const float* __restrict__ res, float* __restrict__ C,
    bf16* __restrict__ Cb, int M, int N, int K)
{
    extern __shared__ char sm[];
    const uint32_t sbase = s2u(sm);
    const int tid = threadIdx.x, lane = tid & 31, wid = tid >> 5;
    const int wm = wid >> 2, wn = wid & 3;
    const int bm = blockIdx.y * 128, bn = blockIdx.x * 128;

    float acc[4][4][4];
    #pragma unroll
    for (int i = 0; i < 4; i++)
        #pragma unroll
        for (int j = 0; j < 4; j++)
            #pragma unroll
            for (int e = 0; e < 4; e++) acc[i][j][e] = 0.f;

    const int a_r = wm * 64 + (lane & 15);
    const int a_c = (lane >> 4) * 8;
    const int b_r = lane & 15;
    const int b_c = wn * 32 + (lane >> 4) * 8;
    const int nch = K >> 5;

    const int ar0 = tid >> 2, as0 = (tid & 3) * 8;
    const int br0 = tid >> 4, bs0 = (tid & 15) * 8;

    auto CP = [&](int c) {
        const int k0 = c << 5;
        const uint32_t base = sbase + (c % 3) * ST1_B;
        #pragma unroll
        for (int i = 0; i < 2; i++) {
            const int row = ar0 + i * 64;
            cpa16(base + A1_B + (uint32_t)(row * A1STR + as0) * 2,
                  Ahi + (size_t)(bm + row) * K + k0 + as0);
        }
        #pragma unroll
        for (int i = 0; i < 2; i++) {
            const int row = br0 + i * 16;
            cpa16(base + B1_B + (uint32_t)(row * B1STR + bs0) * 2,
                  Bhi + (size_t)(k0 + row) * N + bn + bs0);
        }
        CP_COMMIT();
    };
    auto MMAS = [&](int slot) {
        const uint32_t stg = sbase + slot * ST1_B;
        #pragma unroll
        for (int ks = 0; ks < 2; ks++) {
            uint32_t ah[4][4], bh[2][4];
            #pragma unroll
            for (int mi = 0; mi < 4; mi++)
                ldsm4(ah[mi], stg + A1_B +
                      ((a_r + mi * 16) * A1STR + ks * 16 + a_c) * 2);
            #pragma unroll
            for (int np = 0; np < 2; np++)
                ldsm4t(bh[np], stg + B1_B +
                       ((b_r + ks * 16) * B1STR + b_c + np * 16) * 2);
            #pragma unroll
            for (int mi = 0; mi < 4; mi++)
                #pragma unroll
                for (int ni = 0; ni < 4; ni++) {
                    const int np = ni >> 1, pr = (ni & 1) * 2;
                    mma16816(acc[mi][ni], ah[mi], bh[np][pr], bh[np][pr + 1]);
                }
        }
    };

    CP(0);
    CP(1);
    for (int c = 0; c < nch; c++) {
        if (c == nch - 1) CP_WAIT0(); else CP_WAIT1();
        __syncthreads();
        if (c + 2 < nch) CP(c + 2);
        MMAS(c % 3);
    }

    const int g = lane >> 2, t4 = lane & 3;
    #pragma unroll
    for (int mi = 0; mi < 4; mi++) {
        const int r0 = bm + wm * 64 + mi * 16 + g;
        #pragma unroll
        for (int half = 0; half < 2; half++) {
            const int row = r0 + half * 8;
            #pragma unroll
            for (int ni = 0; ni < 4; ni++) {
                const int col = bn + wn * 32 + ni * 8 + t4 * 2;
                float v0 = acc[mi][ni][half * 2 + 0];
                float v1 = acc[mi][ni][half * 2 + 1];
                if (RES) {
                    const float2 rv = *(const float2*)(res + (size_t)row * N + col);
                    v0 += rv.x; v1 += rv.y;
                }
                if (OUTBF)
                    *(uint32_t*)(Cb + (size_t)row * N + col) = packbf(v0, v1);
                else
                    *(float2*)(C + (size_t)row * N + col) = make_float2(v0, v1);
            }
        }
    }
}

// ======================= 3-pass split-bf16 GEMM (FFN) ======================
#define ASTRIDE 40
#define BSTRIDE 136
#define AH_B    0
#define AL_B    10240
#define BH_B    20480
#define BL_B    29184
#define STAGE_B 37888
#define GSMEM   (3*STAGE_B)

template<int BIAS, int RELU, int RES, int SPLIT>
__global__ void __launch_bounds__(256, 2) tc_gemm(
    const bf16* __restrict__ Ahi, const bf16* __restrict__ Alo,
    const bf16* __restrict__ Bhi, const bf16* __restrict__ Blo,
    const float* __restrict__ bias, const float* __restrict__ res,
    float* __restrict__ C, bf16* __restrict__ Chi, bf16* __restrict__ Clo,
    int M, int N, int K)
{
    extern __shared__ char sm[];
    const uint32_t sbase = s2u(sm);
    const int tid = threadIdx.x, lane = tid & 31, wid = tid >> 5;
    const int wm = wid >> 2, wn = wid & 3;
    const int bm = blockIdx.y * 128, bn = blockIdx.x * 128;

    float acc[4][4][4];
    #pragma unroll
    for (int i = 0; i < 4; i++)
        #pragma unroll
        for (int j = 0; j < 4; j++)
            #pragma unroll
            for (int e = 0; e < 4; e++) acc[i][j][e] = 0.f;

    const int a_r = wm * 64 + (lane & 15);
    const int a_c = (lane >> 4) * 8;
    const int b_r = lane & 15;
    const int b_c = wn * 32 + (lane >> 4) * 8;
    const int nch = K >> 5;

    const int ar0 = tid >> 2, as0 = (tid & 3) * 8;
    const int br0 = tid >> 4, bs0 = (tid & 15) * 8;

    auto CP = [&](int c) {
        const int k0 = c << 5;
        const uint32_t base = sbase + (c % 3) * STAGE_B;
        #pragma unroll
        for (int i = 0; i < 2; i++) {
            const int row = ar0 + i * 64;
            const uint32_t d = base + (uint32_t)(row * ASTRIDE + as0) * 2;
            cpa16(d + AH_B, Ahi + (size_t)(bm + row) * K + k0 + as0);
            cpa16(d + AL_B, Alo + (size_t)(bm + row) * K + k0 + as0);
        }
        #pragma unroll
        for (int i = 0; i < 2; i++) {
            const int row = br0 + i * 16;
            const uint32_t d = base + (uint32_t)(row * BSTRIDE + bs0) * 2;
            cpa16(d + BH_B, Bhi + (size_t)(k0 + row) * N + bn + bs0);
            cpa16(d + BL_B, Blo + (size_t)(k0 + row) * N + bn + bs0);
        }
        CP_COMMIT();
    };
    auto MMAS = [&](int slot) {
        const uint32_t stg = sbase + slot * STAGE_B;
        #pragma unroll
        for (int ks = 0; ks < 2; ks++) {
            uint32_t ah[4][4], al[4][4], bh[2][4], bl[2][4];
            #pragma unroll
            for (int mi = 0; mi < 4; mi++) {
                const uint32_t off =
                    ((a_r + mi * 16) * ASTRIDE + ks * 16 + a_c) * 2;
                ldsm4(ah[mi], stg + AH_B + off);
                ldsm4(al[mi], stg + AL_B + off);
            }
            #pragma unroll
            for (int np = 0; np < 2; np++) {
                const uint32_t off =
                    ((b_r + ks * 16) * BSTRIDE + b_c + np * 16) * 2;
                ldsm4t(bh[np], stg + BH_B + off);
                ldsm4t(bl[np], stg + BL_B + off);
            }
            #pragma unroll
            for (int mi = 0; mi < 4; mi++)
                #pragma unroll
                for (int ni = 0; ni < 4; ni++) {
                    const int np = ni >> 1, pr = (ni & 1) * 2;
                    mma16816(acc[mi][ni], ah[mi], bh[np][pr], bh[np][pr + 1]);
                    mma16816(acc[mi][ni], ah[mi], bl[np][pr], bl[np][pr + 1]);
                    mma16816(acc[mi][ni], al[mi], bh[np][pr], bh[np][pr + 1]);
                }
        }
    };

    CP(0);
    CP(1);
    for (int c = 0; c < nch; c++) {
        if (c == nch - 1) CP_WAIT0(); else CP_WAIT1();
        __syncthreads();
        if (c + 2 < nch) CP(c + 2);
        MMAS(c % 3);
    }

    const int g = lane >> 2, t4 = lane & 3;
    #pragma unroll
    for (int mi = 0; mi < 4; mi++) {
        const int r0 = bm + wm * 64 + mi * 16 + g;
        #pragma unroll
        for (int half = 0; half < 2; half++) {
            const int row = r0 + half * 8;
            #pragma unroll
            for (int ni = 0; ni < 4; ni++) {
                const int col = bn + wn * 32 + ni * 8 + t4 * 2;
                float v0 = acc[mi][ni][half * 2 + 0];
                float v1 = acc[mi][ni][half * 2 + 1];
                if (BIAS) { v0 += bias[col]; v1 += bias[col + 1]; }
                if (RELU) { v0 = fmaxf(v0, 0.f); v1 = fmaxf(v1, 0.f); }
                if (RES) {
                    const float2 rv = *(const float2*)(res + (size_t)row * N + col);
                    v0 += rv.x; v1 += rv.y;
                }
                if (SPLIT) {
                    ((uint32_t*)(Chi + (size_t)row * N + col))[0] = packbf(v0, v1);
                    ((uint32_t*)(Clo + (size_t)row * N + col))[0] =
                        packbf(bferr(v0), bferr(v1));
                } else {
                    *(float2*)(C + (size_t)row * N + col) = make_float2(v0, v1);
                }
            }
        }
    }
}

// ---------------- LayerNorm (Bessel var, /(std+eps)) -> bf16 ---------------
template<int LO>
__global__ void ln_kernel(const float* __restrict__ in,
                          const float* __restrict__ alpha,
                          const float* __restrict__ beta,
                          bf16* __restrict__ ohi, bf16* __restrict__ olo)
{
    __shared__ float row[EMB];
    __shared__ float red[8];
    const int r   = blockIdx.x;
    const int tid = threadIdx.x;
    const float* p = in + (size_t)r * EMB;

    float s = 0.f;
    #pragma unroll
    for (int i = tid; i < EMB; i += 256) { float v = p[i]; row[i] = v; s += v; }
    #pragma unroll
    for (int o = 16; o; o >>= 1) s += __shfl_xor_sync(0xffffffffu, s, o);
    if ((tid & 31) == 0) red[tid >> 5] = s;
    __syncthreads();
    if (tid < 8) {
        float t = red[tid];
        #pragma unroll
        for (int o = 4; o; o >>= 1) t += __shfl_xor_sync(0xffu, t, o);
        if (tid == 0) red[0] = t;
    }
    __syncthreads();
    const float mean = red[0] * (1.f / EMB);

    float s2 = 0.f;
    #pragma unroll
    for (int i = tid; i < EMB; i += 256) { float d = row[i] - mean; s2 += d * d; }
    #pragma unroll
    for (int o = 16; o; o >>= 1) s2 += __shfl_xor_sync(0xffffffffu, s2, o);
    __syncthreads();
    if ((tid & 31) == 0) red[tid >> 5] = s2;
    __syncthreads();
    if (tid < 8) {
        float t = red[tid];
        #pragma unroll
        for (int o = 4; o; o >>= 1) t += __shfl_xor_sync(0xffu, t, o);
        if (tid == 0) red[0] = t;
    }
    __syncthreads();
    const float var   = red[0] * (1.f / (EMB - 1));
    const float scale = alpha[0] / (sqrtf(var) + 1e-6f);
    const float bias  = beta[0];

    #pragma unroll
    for (int i = tid; i < EMB; i += 256) {
        const float v = (row[i] - mean) * scale + bias;
        ohi[(size_t)r * EMB + i] = __float2bfloat16(v);
        if (LO) olo[(size_t)r * EMB + i] = __float2bfloat16(bferr(v));
    }
}

// ====== tensor-core flash attention: bf16-hi, cp.async, SW128 swizzle ======
// CTA: 64 queries of one (b,h). 256 thr, 8 warps = 4 m-warps x 2 n-warps.
#define QP_B   0              // Q then P: 64 x 128B
#define KS_B   8192           // 3 stages x 8192
#define VS_B   32768          // 3 stages x 8192
#define RM_B   57344
#define RL_B   57856
#define ASMEM  58368
#define NT     (SQ/64)

__global__ void __launch_bounds__(256, 2) attn_tc(
    const bf16* __restrict__ Qh, const bf16* __restrict__ Kh,
    const bf16* __restrict__ Vh, const int* __restrict__ mask,
    bf16* __restrict__ Oh)
{
    extern __shared__ char asm_[];
    const uint32_t sb = s2u(asm_);
    float* redm = (float*)(asm_ + RM_B);
    float* redl = (float*)(asm_ + RL_B);

    const int b  = blockIdx.z, h = blockIdx.y;
    const int q0 = blockIdx.x * 64;
    const int tid = threadIdx.x, lane = tid & 31, wid = tid >> 5;
    const int wm = wid >> 1, wn = wid & 1;
    const int g = lane >> 2, t4 = lane & 3;
    const size_t base = (size_t)b * SQ * EMB + h * DKH;

    auto CPT = [&](int jt) {
        const int j0 = jt * 64;
        const uint32_t kslot = sb + KS_B + (jt % 3) * 8192;
        const uint32_t vslot = sb + VS_B + (jt % 3) * 8192;
        #pragma unroll
        for (int i = 0; i < 2; i++) {
            const int id = tid + 256 * i, r = id >> 3, ch = id & 7;
            const uint32_t so = swz(r * 128 + ch * 16);
            cpa16(kslot + so, Kh + base + (size_t)(j0 + r) * EMB + ch * 8);
            cpa16(vslot + so, Vh + base + (size_t)(j0 + r) * EMB + ch * 8);
        }
        CP_COMMIT();
    };

    // Q staged with tile-0 group
    #pragma unroll
    for (int i = 0; i < 2; i++) {
        const int id = tid + 256 * i, r = id >> 3, ch = id & 7;
        cpa16(sb + QP_B + swz(r * 128 + ch * 16),
              Qh + base + (size_t)(q0 + r) * EMB + ch * 8);
    }
    CPT(0);
    CPT(1);

    uint32_t qf[4][4];
    float m_r[2] = {-1e30f, -1e30f}, l_r[2] = {0.f, 0.f};
    float acc_o[4][4];
    #pragma unroll
    for (int ni = 0; ni < 4; ni++)
        #pragma unroll
        for (int e = 0; e < 4; e++) acc_o[ni][e] = 0.f;

    for (int jt = 0; jt < NT; jt++) {
        if (jt == NT - 1) CP_WAIT0(); else CP_WAIT1();
        __syncthreads();
        if (jt == 0) {
            const int ar = wm * 16 + (lane & 15);
            #pragma unroll
            for (int ks = 0; ks < 4; ks++)
                ldsm4(qf[ks], sb + QP_B + swz(ar * 128 + ks * 32 + (lane >> 4) * 16));
        }
        const uint32_t kslot = sb + KS_B + (jt % 3) * 8192;
        const uint32_t vslot = sb + VS_B + (jt % 3) * 8192;

        // ---- S = Q @ K^T (B-frags: plain ldsm on natural [key][dk]) ----
        float s[4][4];
        #pragma unroll
        for (int ni = 0; ni < 4; ni++)
            #pragma unroll
            for (int e = 0; e < 4; e++) s[ni][e] = 0.f;
        #pragma unroll
        for (int ks = 0; ks < 4; ks++) {
            uint32_t bh[2][4];
            #pragma unroll
            for (int np = 0; np < 2; np++) {
                const int krow = wn * 32 + np * 16 + (lane & 15);
                ldsm4(bh[np], kslot + swz(krow * 128 + ks * 32 + (lane >> 4) * 16));
            }
            #pragma unroll
            for (int ni = 0; ni < 4; ni++) {
                const int np = ni >> 1, sel = ni & 1;
                mma16816(s[ni], qf[ks], bh[np][sel], bh[np][sel + 2]);
            }
        }

        // ---- scale (1/8) + mask ----
        const int j0 = jt * 64;
        #pragma unroll
        for (int ni = 0; ni < 4; ni++) {
            const int c = j0 + wn * 32 + ni * 8 + t4 * 2;
            int2 mk = *(const int2*)(mask + b * SQ + c);
            s[ni][0] = mk.x ? s[ni][0] * 0.125f : -1e30f;
            s[ni][2] = mk.x ? s[ni][2] * 0.125f : -1e30f;
            s[ni][1] = mk.y ? s[ni][1] * 0.125f : -1e30f;
            s[ni][3] = mk.y ? s[ni][3] * 0.125f : -1e30f;
        }

        // ---- online softmax ----
        float lmax[2] = {-1e30f, -1e30f};
        #pragma unroll
        for (int ni = 0; ni < 4; ni++) {
            lmax[0] = fmaxf(lmax[0], fmaxf(s[ni][0], s[ni][1]));
            lmax[1] = fmaxf(lmax[1], fmaxf(s[ni][2], s[ni][3]));
        }
        #pragma unroll
        for (int o = 1; o <= 2; o <<= 1) {
            lmax[0] = fmaxf(lmax[0], __shfl_xor_sync(0xffffffffu, lmax[0], o));
            lmax[1] = fmaxf(lmax[1], __shfl_xor_sync(0xffffffffu, lmax[1], o));
        }
        if (t4 == 0) {
            redm[wn * 64 + wm * 16 + g] = lmax[0];
            redm[wn * 64 + wm * 16 + g + 8] = lmax[1];
        }
        __syncthreads();
        if (jt + 2 < NT) CPT(jt + 2);   // prefetch overlaps softmax + PV
        float mn[2], corr[2];
        #pragma unroll
        for (int r = 0; r < 2; r++) {
            const int row = wm * 16 + g + r * 8;
            const float tm = fmaxf(redm[row], redm[64 + row]);
            mn[r] = fmaxf(m_r[r], tm);
            corr[r] = __expf(m_r[r] - mn[r]);
            m_r[r] = mn[r];
        }
        float lsum[2] = {0.f, 0.f};
        #pragma unroll
        for (int ni = 0; ni < 4; ni++) {
            float p0 = __expf(s[ni][0] - mn[0]);
            float p1 = __expf(s[ni][1] - mn[0]);
            float p2 = __expf(s[ni][2] - mn[1]);
            float p3 = __expf(s[ni][3] - mn[1]);
            lsum[0] += p0 + p1; lsum[1] += p2 + p3;
            const int colb = (wn * 32 + ni * 8 + t4 * 2) * 2;
            *(uint32_t*)(asm_ + QP_B + swz((wm * 16 + g) * 128 + colb)) =
                packbf(p0, p1);
            *(uint32_t*)(asm_ + QP_B + swz((wm * 16 + g + 8) * 128 + colb)) =
                packbf(p2, p3);
        }
        #pragma unroll
        for (int o = 1; o <= 2; o <<= 1) {
            lsum[0] += __shfl_xor_sync(0xffffffffu, lsum[0], o);
            lsum[1] += __shfl_xor_sync(0xffffffffu, lsum[1], o);
        }
        if (t4 == 0) {
            redl[wn * 64 + wm * 16 + g] = lsum[0];
            redl[wn * 64 + wm * 16 + g + 8] = lsum[1];
        }
        __syncthreads();
        #pragma unroll
        for (int r = 0; r < 2; r++) {
            const int row = wm * 16 + g + r * 8;
            l_r[r] = l_r[r] * corr[r] + redl[row] + redl[64 + row];
        }
        #pragma unroll
        for (int ni = 0; ni < 4; ni++) {
            acc_o[ni][0] *= corr[0]; acc_o[ni][1] *= corr[0];
            acc_o[ni][2] *= corr[1]; acc_o[ni][3] *= corr[1];
        }

        // ---- O += P @ V ----
        #pragma unroll
        for (int ks = 0; ks < 4; ks++) {
            uint32_t pf[4], vf[2][4];
            ldsm4(pf, sb + QP_B +
                  swz((wm * 16 + (lane & 15)) * 128 + ks * 32 + (lane >> 4) * 16));
            #pragma unroll
            for (int np = 0; np < 2; np++)
                ldsm4t(vf[np], vslot +
                       swz(((lane & 15) + ks * 16) * 128
                           + (wn * 32 + np * 16 + (lane >> 4) * 8) * 2));
            #pragma unroll
            for (int ni = 0; ni < 4; ni++) {
                const int np = ni >> 1, pr = (ni & 1) * 2;
                mma16816(acc_o[ni], pf, vf[np][pr], vf[np][pr + 1]);
            }
        }
    }

    // ---- write O as bf16 ----
    const float inv0 = 1.f / l_r[0], inv1 = 1.f / l_r[1];
    #pragma unroll
    for (int r = 0; r < 2; r++) {
        const int qrow = q0 + wm * 16 + g + r * 8;
        const size_t ob = (size_t)(b * SQ + qrow) * EMB + h * DKH;
        const float inv = r ? inv1 : inv0;
        #pragma unroll
        for (int ni = 0; ni < 4; ni++) {
            const int col = wn * 32 + ni * 8 + t4 * 2;
            *(uint32_t*)(Oh + ob + col) =
                packbf(acc_o[ni][r * 2 + 0] * inv, acc_o[ni][r * 2 + 1] * inv);
        }
    }
}

// ---------------------------- launcher -------------------------------------
extern "C" void kernel_launch(void* const* d_in, const int* in_sizes, int n_in,
                              void* d_out, int out_size)
{
    const float* x    = (const float*)d_in[0];
    const int*   mask = (const int*)  d_in[1];
    const float* wq   = (const float*)d_in[2];
    const float* wk   = (const float*)d_in[3];
    const float* wv   = (const float*)d_in[4];
    const float* wo   = (const float*)d_in[5];
    const float* f1w  = (const float*)d_in[6];
    const float* f1b  = (const float*)d_in[7];
    const float* f2w  = (const float*)d_in[8];
    const float* f2b  = (const float*)d_in[9];
    const float* l1a  = (const float*)d_in[10];
    const float* l1b  = (const float*)d_in[11];
    const float* l2a  = (const float*)d_in[12];
    const float* l2b  = (const float*)d_in[13];
    float* out = (float*)d_out;

    float *h;
    bf16 *qh, *kh, *vh, *xnh, *ath, *hnh, *hnl, *ach, *acl;
    bf16 *wqh, *wkh, *wvh, *woh, *f1h, *f1l, *f2h, *f2l;
    cudaGetSymbolAddress((void**)&h,   g_h);
    cudaGetSymbolAddress((void**)&qh,  g_qh);
    cudaGetSymbolAddress((void**)&kh,  g_kh);
    cudaGetSymbolAddress((void**)&vh,  g_vh);
    cudaGetSymbolAddress((void**)&xnh, g_xnh);
    cudaGetSymbolAddress((void**)&ath, g_ath);
    cudaGetSymbolAddress((void**)&hnh, g_hnh); cudaGetSymbolAddress((void**)&hnl, g_hnl);
    cudaGetSymbolAddress((void**)&ach, g_ach); cudaGetSymbolAddress((void**)&acl, g_acl);
    cudaGetSymbolAddress((void**)&wqh, g_wqh);
    cudaGetSymbolAddress((void**)&wkh, g_wkh);
    cudaGetSymbolAddress((void**)&wvh, g_wvh);
    cudaGetSymbolAddress((void**)&woh, g_woh);
    cudaGetSymbolAddress((void**)&f1h, g_f1h); cudaGetSymbolAddress((void**)&f1l, g_f1l);
    cudaGetSymbolAddress((void**)&f2h, g_f2h); cudaGetSymbolAddress((void**)&f2l, g_f2l);

    cudaFuncSetAttribute(tc_gemm1<0,1>, cudaFuncAttributeMaxDynamicSharedMemorySize, G1SMEM);
    cudaFuncSetAttribute(tc_gemm1<1,0>, cudaFuncAttributeMaxDynamicSharedMemorySize, G1SMEM);
    cudaFuncSetAttribute(tc_gemm<1,1,0,1>, cudaFuncAttributeMaxDynamicSharedMemorySize, GSMEM);
    cudaFuncSetAttribute(tc_gemm<1,0,1,0>, cudaFuncAttributeMaxDynamicSharedMemorySize, GSMEM);
    cudaFuncSetAttribute(attn_tc, cudaFuncAttributeMaxDynamicSharedMemorySize, ASMEM);

    // 0. weight splits (hi-only for attention-path weights, hi/lo for FFN)
    const int n2e = EMB * EMB / 2, n2f = EMB * HID / 2;
    split_k<0><<<n2e / 256, 256>>>(wq,  wqh, nullptr, n2e);
    split_k<0><<<n2e / 256, 256>>>(wk,  wkh, nullptr, n2e);
    split_k<0><<<n2e / 256, 256>>>(wv,  wvh, nullptr, n2e);
    split_k<0><<<n2e / 256, 256>>>(wo,  woh, nullptr, n2e);
    split_k<1><<<n2f / 256, 256>>>(f1w, f1h, f1l, n2f);
    split_k<1><<<n2f / 256, 256>>>(f2w, f2h, f2l, n2f);

    // 1. ln1 -> xn (bf16 hi)
    ln_kernel<0><<<MTOT, 256>>>(x, l1a, l1b, xnh, nullptr);
    // 2. QKV projections (1-pass, bf16 out)
    dim3 gEE(EMB / 128, MTOT / 128);
    tc_gemm1<0,1><<<gEE, 256, G1SMEM>>>(xnh, wqh, nullptr, nullptr, qh, MTOT, EMB, EMB);
    tc_gemm1<0,1><<<gEE, 256, G1SMEM>>>(xnh, wkh, nullptr, nullptr, kh, MTOT, EMB, EMB);
    tc_gemm1<0,1><<<gEE, 256, G1SMEM>>>(xnh, wvh, nullptr, nullptr, vh, MTOT, EMB, EMB);
    // 3. attention (bf16 in/out)
    attn_tc<<<dim3(SQ / 64, NH, BATCH), 256, ASMEM>>>(qh, kh, vh, mask, ath);
    // 4. output projection + residual -> h fp32 (1-pass)
    tc_gemm1<1,0><<<gEE, 256, G1SMEM>>>(ath, woh, x, h, nullptr, MTOT, EMB, EMB);
    // 5. ln2 -> hn hi/lo
    ln_kernel<1><<<MTOT, 256>>>(h, l2a, l2b, hnh, hnl);
    // 6. FFN (3-pass split)
    tc_gemm<1,1,0,1><<<dim3(HID / 128, MTOT / 128), 256, GSMEM>>>(
        hnh, hnl, f1h, f1l, f1b, nullptr, nullptr, ach, acl, MTOT, HID, EMB);
    tc_gemm<1,0,1,0><<<gEE, 256, GSMEM>>>(ach, acl, f2h, f2l, f2b, h,
                                          out, nullptr, nullptr, MTOT, EMB, HID);
}